// round 6
// baseline (speedup 1.0000x reference)
#include <cuda_runtime.h>
#include <cuda_bf16.h>
#include <math.h>

// Problem constants (fixed by the dataset)
#define BATCH 2
#define SEQ 2048
#define DMODEL 1536
#define NHEADS 16
#define NGROUPS 4
#define HDIM 96
#define QKV_OUT 2304            // 16*96 + 2*4*96
#define ROWS (BATCH * SEQ)      // 4096

// Scratch (allocation-free rule: __device__ globals)
__device__ float g_qkv[(size_t)ROWS * QKV_OUT];   // ~37.7 MB
__device__ float g_attn[(size_t)ROWS * DMODEL];   // ~25.2 MB

// ---------------------------------------------------------------------------
// GEMM: C[M,N] = A[M,K] * B[N,K]^T   (both operands K-major, "NT" layout)
// 64x64 tile, BK=16, 256 threads, 4x4 accumulators per thread.
// ---------------------------------------------------------------------------
#define BM 64
#define BN 64
#define BKK 16

__global__ __launch_bounds__(256) void gemm_nt(const float* __restrict__ A,
                                               const float* __restrict__ B,
                                               float* __restrict__ C,
                                               int M, int N, int K) {
    __shared__ float As[BKK][BM + 4];
    __shared__ float Bs[BKK][BN + 4];

    const int tid = threadIdx.x;
    const int tx = tid & 15;        // 0..15  (N direction)
    const int ty = tid >> 4;        // 0..15  (M direction)
    const int row0 = blockIdx.y * BM;
    const int col0 = blockIdx.x * BN;

    float acc[4][4];
#pragma unroll
    for (int i = 0; i < 4; i++)
#pragma unroll
        for (int j = 0; j < 4; j++) acc[i][j] = 0.f;

    const int lr = tid >> 2;            // 0..63 row within tile
    const int lk = (tid & 3) << 2;      // 0,4,8,12 k offset

    for (int k0 = 0; k0 < K; k0 += BKK) {
        float4 va = *(const float4*)(A + (size_t)(row0 + lr) * K + k0 + lk);
        float4 vb = *(const float4*)(B + (size_t)(col0 + lr) * K + k0 + lk);
        As[lk + 0][lr] = va.x; As[lk + 1][lr] = va.y;
        As[lk + 2][lr] = va.z; As[lk + 3][lr] = va.w;
        Bs[lk + 0][lr] = vb.x; Bs[lk + 1][lr] = vb.y;
        Bs[lk + 2][lr] = vb.z; Bs[lk + 3][lr] = vb.w;
        __syncthreads();

#pragma unroll
        for (int kk = 0; kk < BKK; kk++) {
            float a[4], b[4];
#pragma unroll
            for (int i = 0; i < 4; i++) a[i] = As[kk][ty * 4 + i];
#pragma unroll
            for (int j = 0; j < 4; j++) b[j] = Bs[kk][tx * 4 + j];
#pragma unroll
            for (int i = 0; i < 4; i++)
#pragma unroll
                for (int j = 0; j < 4; j++) acc[i][j] += a[i] * b[j];
        }
        __syncthreads();
    }

#pragma unroll
    for (int i = 0; i < 4; i++) {
        float* crow = C + (size_t)(row0 + ty * 4 + i) * N + col0 + tx * 4;
        float4 v = make_float4(acc[i][0], acc[i][1], acc[i][2], acc[i][3]);
        *(float4*)crow = v;
    }
}

// ---------------------------------------------------------------------------
// RoPE-3D: rotate q (16 heads) and k (4 groups) in-place inside g_qkv.
// One thread per (row, head, pair). 20 heads total (16 q + 4 k), 48 pairs.
// ---------------------------------------------------------------------------
__global__ void rope_kernel(float* __restrict__ qkv,
                            const int* __restrict__ p_gh,
                            const int* __restrict__ p_gw) {
    int idx = blockIdx.x * blockDim.x + threadIdx.x;
    const int TOTAL = ROWS * 20 * 48;
    if (idx >= TOTAL) return;

    int pair = idx % 48;
    int head = (idx / 48) % 20;
    int row = idx / (48 * 20);
    int n = row % SEQ;

    int H = p_gh ? *p_gh : 16;
    int W = p_gw ? *p_gw : 16;
    int w = n % W;
    int h = (n / W) % H;
    int t = n / (W * H);

    int axis = pair / 16;         // 0:t 1:h 2:w
    int i = pair % 16;            // rotation pair within axis (P=16)
    float pos = (float)(axis == 0 ? t : (axis == 1 ? h : w));

    float freq = powf(10000.f, -(float)i / 16.f);
    float ang = pos * freq;
    float s, c;
    sincosf(ang, &s, &c);

    int coloff = (head < 16) ? head * HDIM : (1536 + (head - 16) * HDIM);
    size_t base = (size_t)row * QKV_OUT + coloff + axis * 32 + 2 * i;
    float x0 = qkv[base];
    float x1 = qkv[base + 1];
    qkv[base] = x0 * c - x1 * s;
    qkv[base + 1] = x0 * s + x1 * c;
}

// ---------------------------------------------------------------------------
// Flash-style GQA attention. grid = (qblocks=16, heads=16, batch=2),
// 128 threads/block, 1 thread = 1 query row. Online softmax, K/V tiles of 32
// staged in smem (k_j[d] / v_j[d] reads are warp-broadcast -> conflict-free).
// ---------------------------------------------------------------------------
#define TKEY 32

__global__ __launch_bounds__(128) void attn_kernel(const float* __restrict__ qkv,
                                                   float* __restrict__ out) {
    __shared__ float Ks[TKEY][HDIM];
    __shared__ float Vs[TKEY][HDIM];

    const int b = blockIdx.z;
    const int hh = blockIdx.y;
    const int q = blockIdx.x * 128 + threadIdx.x;
    const int g = hh >> 2;  // repeat_interleave: head h uses group h/4

    const float scale = rsqrtf((float)HDIM);

    // Load this thread's query row (pre-scaled).
    float qreg[HDIM];
    {
        const float* qrow = qkv + ((size_t)(b * SEQ + q)) * QKV_OUT + hh * HDIM;
#pragma unroll
        for (int d = 0; d < HDIM; d++) qreg[d] = qrow[d] * scale;
    }

    float acc[HDIM];
#pragma unroll
    for (int d = 0; d < HDIM; d++) acc[d] = 0.f;
    float m = -1e30f;
    float l = 0.f;

    for (int k0 = 0; k0 < SEQ; k0 += TKEY) {
        __syncthreads();
        // stage K/V tile: TKEY*HDIM = 3072 floats each, coalesced
        for (int idx = threadIdx.x; idx < TKEY * HDIM; idx += 128) {
            int kk = idx / HDIM;
            int d = idx % HDIM;
            size_t rb = ((size_t)(b * SEQ + k0 + kk)) * QKV_OUT + 1536 + g * HDIM;
            Ks[kk][d] = __ldg(qkv + rb + d);
            Vs[kk][d] = __ldg(qkv + rb + 384 + d);
        }
        __syncthreads();

#pragma unroll 1
        for (int j = 0; j < TKEY; j++) {
            // s = q . k_j  (k_j reads are broadcast across the warp)
            float s = 0.f;
            const float4* kp = reinterpret_cast<const float4*>(&Ks[j][0]);
#pragma unroll
            for (int d4 = 0; d4 < HDIM / 4; d4++) {
                float4 kv = kp[d4];
                s += qreg[4 * d4 + 0] * kv.x;
                s += qreg[4 * d4 + 1] * kv.y;
                s += qreg[4 * d4 + 2] * kv.z;
                s += qreg[4 * d4 + 3] * kv.w;
            }

            float mnew = fmaxf(m, s);
            if (mnew > m) {
                float corr = expf(m - mnew);
                l *= corr;
#pragma unroll
                for (int d = 0; d < HDIM; d++) acc[d] *= corr;
                m = mnew;
            }
            float p = expf(s - m);
            l += p;

            const float4* vp = reinterpret_cast<const float4*>(&Vs[j][0]);
#pragma unroll
            for (int d4 = 0; d4 < HDIM / 4; d4++) {
                float4 vv = vp[d4];
                acc[4 * d4 + 0] += p * vv.x;
                acc[4 * d4 + 1] += p * vv.y;
                acc[4 * d4 + 2] += p * vv.z;
                acc[4 * d4 + 3] += p * vv.w;
            }
        }
    }

    float inv = 1.f / l;
    float* orow = out + ((size_t)(b * SEQ + q)) * DMODEL + hh * HDIM;
#pragma unroll
    for (int d = 0; d < HDIM; d++) orow[d] = acc[d] * inv;
}

// ---------------------------------------------------------------------------
extern "C" void kernel_launch(void* const* d_in, const int* in_sizes, int n_in,
                              void* d_out, int out_size) {
    const float* x = (const float*)d_in[0];
    const float* w_qkv = (const float*)d_in[1];
    const float* w_o = (const float*)d_in[2];
    const int* gh = (n_in >= 6) ? (const int*)d_in[4] : nullptr;
    const int* gw = (n_in >= 6) ? (const int*)d_in[5] : nullptr;
    float* out = (float*)d_out;

    float* qkv = nullptr;
    float* attn = nullptr;
    cudaGetSymbolAddress((void**)&qkv, g_qkv);
    cudaGetSymbolAddress((void**)&attn, g_attn);

    // 1) QKV projection: [4096,1536] x [2304,1536]^T -> [4096,2304]
    {
        dim3 grid(QKV_OUT / BN, ROWS / BM);
        gemm_nt<<<grid, 256>>>(x, w_qkv, qkv, ROWS, QKV_OUT, DMODEL);
    }

    // 2) RoPE on q and k slices
    {
        int total = ROWS * 20 * 48;
        int threads = 256;
        rope_kernel<<<(total + threads - 1) / threads, threads>>>(qkv, gh, gw);
    }

    // 3) GQA flash attention -> g_attn [4096, 1536]
    {
        dim3 grid(SEQ / 128, NHEADS, BATCH);
        attn_kernel<<<grid, 128>>>(qkv, attn);
    }

    // 4) Output projection: [4096,1536] x [1536,1536]^T -> d_out
    {
        dim3 grid(DMODEL / BN, ROWS / BM);
        gemm_nt<<<grid, 256>>>(attn, w_o, out, ROWS, DMODEL, DMODEL);
    }
}

// round 7
// speedup vs baseline: 1.1542x; 1.1542x over previous
#include <cuda_runtime.h>
#include <cuda_bf16.h>
#include <math.h>

// Problem constants (fixed by the dataset)
#define BATCH 2
#define SEQ 2048
#define DMODEL 1536
#define NHEADS 16
#define NGROUPS 4
#define HDIM 96
#define QKV_OUT 2304            // 16*96 + 2*4*96
#define ROWS (BATCH * SEQ)      // 4096

// Scratch (allocation-free rule: __device__ globals)
__device__ float g_qkv[(size_t)ROWS * QKV_OUT];   // ~37.7 MB
__device__ float g_attn[(size_t)ROWS * DMODEL];   // ~25.2 MB

// ---------------------------------------------------------------------------
// TF32 helpers (3xTF32 decomposition: fp32-comparable accuracy on tensor pipe)
// ---------------------------------------------------------------------------
__device__ __forceinline__ unsigned f2tf(float x) {
    unsigned r;
    asm("cvt.rna.tf32.f32 %0, %1;" : "=r"(r) : "f"(x));
    return r;
}

__device__ __forceinline__ void mma_tf32(float d[4], const unsigned a[4], const unsigned b[2]) {
    asm volatile(
        "mma.sync.aligned.m16n8k8.row.col.f32.tf32.tf32.f32 "
        "{%0,%1,%2,%3}, {%4,%5,%6,%7}, {%8,%9}, {%0,%1,%2,%3};\n"
        : "+f"(d[0]), "+f"(d[1]), "+f"(d[2]), "+f"(d[3])
        : "r"(a[0]), "r"(a[1]), "r"(a[2]), "r"(a[3]), "r"(b[0]), "r"(b[1]));
}

// ---------------------------------------------------------------------------
// Tensor-core GEMM: C[M,N] = A[M,K] * B[N,K]^T  (both K-major, "NT")
// 128x128 block tile, BK=16, 256 threads (8 warps, 4x2), warp tile 32x64.
// 3xTF32: each mma position issues hi*hi + hi*lo + lo*hi.
// Smem row stride 20 floats: 8 rows x 4 k-cols hit 32 distinct banks.
// ---------------------------------------------------------------------------
#define GBM 128
#define GBN 128
#define GBK 16
#define GST 20   // padded smem row stride (floats)

__global__ __launch_bounds__(256, 1) void gemm_tf32(const float* __restrict__ A,
                                                    const float* __restrict__ B,
                                                    float* __restrict__ C,
                                                    int M, int N, int K) {
    __shared__ float As[GBM * GST];   // 10240 B
    __shared__ float Bs[GBN * GST];   // 10240 B

    const int tid = threadIdx.x;
    const int lane = tid & 31;
    const int warp = tid >> 5;
    const int gid = lane >> 2;      // 0..7
    const int tig = lane & 3;       // 0..3
    const int wm = (warp >> 1) * 32;   // warp M offset (0,32,64,96)
    const int wn = (warp & 1) * 64;    // warp N offset (0,64)
    const int row0 = blockIdx.y * GBM;
    const int col0 = blockIdx.x * GBN;

    // global->smem loader mapping: 256 threads x 2 float4 per operand
    const int lr = tid >> 2;            // 0..63
    const int lc = (tid & 3) << 2;      // 0,4,8,12

    const float* Ap0 = A + (size_t)(row0 + lr) * K + lc;
    const float* Ap1 = A + (size_t)(row0 + lr + 64) * K + lc;
    const float* Bp0 = B + (size_t)(col0 + lr) * K + lc;
    const float* Bp1 = B + (size_t)(col0 + lr + 64) * K + lc;

    float acc[2][8][4];
#pragma unroll
    for (int mi = 0; mi < 2; mi++)
#pragma unroll
        for (int ni = 0; ni < 8; ni++)
#pragma unroll
            for (int r = 0; r < 4; r++) acc[mi][ni][r] = 0.f;

    // prefetch first tile into registers
    float4 fa0 = *(const float4*)(Ap0);
    float4 fa1 = *(const float4*)(Ap1);
    float4 fb0 = *(const float4*)(Bp0);
    float4 fb1 = *(const float4*)(Bp1);

    for (int k0 = 0; k0 < K; k0 += GBK) {
        *(float4*)&As[lr * GST + lc]        = fa0;
        *(float4*)&As[(lr + 64) * GST + lc] = fa1;
        *(float4*)&Bs[lr * GST + lc]        = fb0;
        *(float4*)&Bs[(lr + 64) * GST + lc] = fb1;
        __syncthreads();

        // issue next tile's LDGs early; latency hidden behind mma work
        if (k0 + GBK < K) {
            fa0 = *(const float4*)(Ap0 + k0 + GBK);
            fa1 = *(const float4*)(Ap1 + k0 + GBK);
            fb0 = *(const float4*)(Bp0 + k0 + GBK);
            fb1 = *(const float4*)(Bp1 + k0 + GBK);
        }

#pragma unroll
        for (int ks = 0; ks < 2; ks++) {
            const int kk = ks * 8 + tig;

            // A fragments (m16 x k8), 2 m-tiles
            unsigned ahi[2][4], alo[2][4];
#pragma unroll
            for (int mi = 0; mi < 2; mi++) {
                int rb = (wm + mi * 16 + gid) * GST + kk;
                float x0 = As[rb];
                float x1 = As[rb + 8 * GST];
                float x2 = As[rb + 4];
                float x3 = As[rb + 8 * GST + 4];
                ahi[mi][0] = f2tf(x0); alo[mi][0] = f2tf(x0 - __uint_as_float(ahi[mi][0]));
                ahi[mi][1] = f2tf(x1); alo[mi][1] = f2tf(x1 - __uint_as_float(ahi[mi][1]));
                ahi[mi][2] = f2tf(x2); alo[mi][2] = f2tf(x2 - __uint_as_float(ahi[mi][2]));
                ahi[mi][3] = f2tf(x3); alo[mi][3] = f2tf(x3 - __uint_as_float(ahi[mi][3]));
            }

            // B fragments (k8 x n8), 8 n-tiles
            unsigned bhi[8][2], blo[8][2];
#pragma unroll
            for (int ni = 0; ni < 8; ni++) {
                int rb = (wn + ni * 8 + gid) * GST + kk;
                float y0 = Bs[rb];
                float y1 = Bs[rb + 4];
                bhi[ni][0] = f2tf(y0); blo[ni][0] = f2tf(y0 - __uint_as_float(bhi[ni][0]));
                bhi[ni][1] = f2tf(y1); blo[ni][1] = f2tf(y1 - __uint_as_float(bhi[ni][1]));
            }

#pragma unroll
            for (int mi = 0; mi < 2; mi++)
#pragma unroll
                for (int ni = 0; ni < 8; ni++) {
                    mma_tf32(acc[mi][ni], ahi[mi], bhi[ni]);
                    mma_tf32(acc[mi][ni], ahi[mi], blo[ni]);
                    mma_tf32(acc[mi][ni], alo[mi], bhi[ni]);
                }
        }
        __syncthreads();
    }

    // epilogue: c0,c1 -> (row=gid, col=tig*2..+1); c2,c3 -> row=gid+8
#pragma unroll
    for (int mi = 0; mi < 2; mi++)
#pragma unroll
        for (int ni = 0; ni < 8; ni++) {
            int r = row0 + wm + mi * 16 + gid;
            int c = col0 + wn + ni * 8 + (tig << 1);
            *(float2*)&C[(size_t)r * N + c]       = make_float2(acc[mi][ni][0], acc[mi][ni][1]);
            *(float2*)&C[(size_t)(r + 8) * N + c] = make_float2(acc[mi][ni][2], acc[mi][ni][3]);
        }
}

// ---------------------------------------------------------------------------
// RoPE-3D: rotate q (16 heads) and k (4 groups) in-place inside g_qkv.
// One thread per (row, head, pair). 20 heads total (16 q + 4 k), 48 pairs.
// ---------------------------------------------------------------------------
__global__ void rope_kernel(float* __restrict__ qkv,
                            const int* __restrict__ p_gh,
                            const int* __restrict__ p_gw) {
    int idx = blockIdx.x * blockDim.x + threadIdx.x;
    const int TOTAL = ROWS * 20 * 48;
    if (idx >= TOTAL) return;

    int pair = idx % 48;
    int head = (idx / 48) % 20;
    int row = idx / (48 * 20);
    int n = row % SEQ;

    int H = p_gh ? *p_gh : 16;
    int W = p_gw ? *p_gw : 16;
    int w = n % W;
    int h = (n / W) % H;
    int t = n / (W * H);

    int axis = pair / 16;         // 0:t 1:h 2:w
    int i = pair % 16;            // rotation pair within axis (P=16)
    float pos = (float)(axis == 0 ? t : (axis == 1 ? h : w));

    float freq = powf(10000.f, -(float)i / 16.f);
    float ang = pos * freq;
    float s, c;
    sincosf(ang, &s, &c);

    int coloff = (head < 16) ? head * HDIM : (1536 + (head - 16) * HDIM);
    size_t base = (size_t)row * QKV_OUT + coloff + axis * 32 + 2 * i;
    float x0 = qkv[base];
    float x1 = qkv[base + 1];
    qkv[base] = x0 * c - x1 * s;
    qkv[base + 1] = x0 * s + x1 * c;
}

// ---------------------------------------------------------------------------
// Flash-style GQA attention. grid = (qblocks=16, heads=16, batch=2),
// 128 threads/block, 1 thread = 1 query row. Online softmax, K/V tiles of 32
// staged in smem (k_j/v_j reads are warp-broadcast -> conflict-free).
// ---------------------------------------------------------------------------
#define TKEY 32

__global__ __launch_bounds__(128) void attn_kernel(const float* __restrict__ qkv,
                                                   float* __restrict__ out) {
    __shared__ float Ks[TKEY][HDIM];
    __shared__ float Vs[TKEY][HDIM];

    const int b = blockIdx.z;
    const int hh = blockIdx.y;
    const int q = blockIdx.x * 128 + threadIdx.x;
    const int g = hh >> 2;  // repeat_interleave: head h uses group h/4

    const float scale = rsqrtf((float)HDIM);

    // Load this thread's query row (pre-scaled).
    float qreg[HDIM];
    {
        const float* qrow = qkv + ((size_t)(b * SEQ + q)) * QKV_OUT + hh * HDIM;
#pragma unroll
        for (int d = 0; d < HDIM; d++) qreg[d] = qrow[d] * scale;
    }

    float acc[HDIM];
#pragma unroll
    for (int d = 0; d < HDIM; d++) acc[d] = 0.f;
    float m = -1e30f;
    float l = 0.f;

    for (int k0 = 0; k0 < SEQ; k0 += TKEY) {
        __syncthreads();
        // stage K/V tile: TKEY*HDIM = 3072 floats each, coalesced
        for (int idx = threadIdx.x; idx < TKEY * HDIM; idx += 128) {
            int kk = idx / HDIM;
            int d = idx % HDIM;
            size_t rb = ((size_t)(b * SEQ + k0 + kk)) * QKV_OUT + 1536 + g * HDIM;
            Ks[kk][d] = __ldg(qkv + rb + d);
            Vs[kk][d] = __ldg(qkv + rb + 384 + d);
        }
        __syncthreads();

#pragma unroll 1
        for (int j = 0; j < TKEY; j++) {
            // s = q . k_j  (k_j reads are broadcast across the warp)
            float s = 0.f;
            const float4* kp = reinterpret_cast<const float4*>(&Ks[j][0]);
#pragma unroll
            for (int d4 = 0; d4 < HDIM / 4; d4++) {
                float4 kv = kp[d4];
                s += qreg[4 * d4 + 0] * kv.x;
                s += qreg[4 * d4 + 1] * kv.y;
                s += qreg[4 * d4 + 2] * kv.z;
                s += qreg[4 * d4 + 3] * kv.w;
            }

            float mnew = fmaxf(m, s);
            if (mnew > m) {
                float corr = __expf(m - mnew);
                l *= corr;
#pragma unroll
                for (int d = 0; d < HDIM; d++) acc[d] *= corr;
                m = mnew;
            }
            float p = __expf(s - m);
            l += p;

            const float4* vp = reinterpret_cast<const float4*>(&Vs[j][0]);
#pragma unroll
            for (int d4 = 0; d4 < HDIM / 4; d4++) {
                float4 vv = vp[d4];
                acc[4 * d4 + 0] += p * vv.x;
                acc[4 * d4 + 1] += p * vv.y;
                acc[4 * d4 + 2] += p * vv.z;
                acc[4 * d4 + 3] += p * vv.w;
            }
        }
    }

    float inv = 1.f / l;
    float* orow = out + ((size_t)(b * SEQ + q)) * DMODEL + hh * HDIM;
#pragma unroll
    for (int d = 0; d < HDIM; d++) orow[d] = acc[d] * inv;
}

// ---------------------------------------------------------------------------
extern "C" void kernel_launch(void* const* d_in, const int* in_sizes, int n_in,
                              void* d_out, int out_size) {
    const float* x = (const float*)d_in[0];
    const float* w_qkv = (const float*)d_in[1];
    const float* w_o = (const float*)d_in[2];
    const int* gh = (n_in >= 6) ? (const int*)d_in[4] : nullptr;
    const int* gw = (n_in >= 6) ? (const int*)d_in[5] : nullptr;
    float* out = (float*)d_out;

    float* qkv = nullptr;
    float* attn = nullptr;
    cudaGetSymbolAddress((void**)&qkv, g_qkv);
    cudaGetSymbolAddress((void**)&attn, g_attn);

    // 1) QKV projection: [4096,1536] x [2304,1536]^T -> [4096,2304]
    {
        dim3 grid(QKV_OUT / GBN, ROWS / GBM);   // 18 x 32
        gemm_tf32<<<grid, 256>>>(x, w_qkv, qkv, ROWS, QKV_OUT, DMODEL);
    }

    // 2) RoPE on q and k slices
    {
        int total = ROWS * 20 * 48;
        int threads = 256;
        rope_kernel<<<(total + threads - 1) / threads, threads>>>(qkv, gh, gw);
    }

    // 3) GQA flash attention -> g_attn [4096, 1536]
    {
        dim3 grid(SEQ / 128, NHEADS, BATCH);
        attn_kernel<<<grid, 128>>>(qkv, attn);
    }

    // 4) Output projection: [4096,1536] x [1536,1536]^T -> d_out
    {
        dim3 grid(DMODEL / GBN, ROWS / GBM);    // 12 x 32
        gemm_tf32<<<grid, 256>>>(attn, w_o, out, ROWS, DMODEL, DMODEL);
    }
}

// round 9
// speedup vs baseline: 1.7074x; 1.4793x over previous
#include <cuda_runtime.h>
#include <cuda_bf16.h>
#include <math.h>

// Problem constants (fixed by the dataset)
#define BATCH 2
#define SEQ 2048
#define DMODEL 1536
#define NHEADS 16
#define NGROUPS 4
#define HDIM 96
#define QKV_OUT 2304            // 16*96 + 2*4*96
#define ROWS (BATCH * SEQ)      // 4096

// Scratch (allocation-free rule: __device__ globals)
__device__ float g_qkv[(size_t)ROWS * QKV_OUT];   // ~37.7 MB
__device__ float g_attn[(size_t)ROWS * DMODEL];   // ~25.2 MB

// ---------------------------------------------------------------------------
// TF32 helpers (3xTF32 decomposition: fp32-comparable accuracy on tensor pipe)
// ---------------------------------------------------------------------------
__device__ __forceinline__ unsigned f2tf(float x) {
    unsigned r;
    asm("cvt.rna.tf32.f32 %0, %1;" : "=r"(r) : "f"(x));
    return r;
}

__device__ __forceinline__ void mma_tf32(float d[4], const unsigned a[4], const unsigned b[2]) {
    asm volatile(
        "mma.sync.aligned.m16n8k8.row.col.f32.tf32.tf32.f32 "
        "{%0,%1,%2,%3}, {%4,%5,%6,%7}, {%8,%9}, {%0,%1,%2,%3};\n"
        : "+f"(d[0]), "+f"(d[1]), "+f"(d[2]), "+f"(d[3])
        : "r"(a[0]), "r"(a[1]), "r"(a[2]), "r"(a[3]), "r"(b[0]), "r"(b[1]));
}

// ---------------------------------------------------------------------------
// Tensor-core GEMM: C[M,N] = A[M,K] * B[N,K]^T  (both K-major, "NT")
// 128x128 block tile, BK=16, 256 threads (8 warps, 4x2), warp tile 32x64.
// ---------------------------------------------------------------------------
#define GBM 128
#define GBN 128
#define GBK 16
#define GST 20   // padded smem row stride (floats)

__global__ __launch_bounds__(256, 1) void gemm_tf32(const float* __restrict__ A,
                                                    const float* __restrict__ B,
                                                    float* __restrict__ C,
                                                    int M, int N, int K) {
    __shared__ float As[GBM * GST];
    __shared__ float Bs[GBN * GST];

    const int tid = threadIdx.x;
    const int lane = tid & 31;
    const int warp = tid >> 5;
    const int gid = lane >> 2;
    const int tig = lane & 3;
    const int wm = (warp >> 1) * 32;
    const int wn = (warp & 1) * 64;
    const int row0 = blockIdx.y * GBM;
    const int col0 = blockIdx.x * GBN;

    const int lr = tid >> 2;
    const int lc = (tid & 3) << 2;

    const float* Ap0 = A + (size_t)(row0 + lr) * K + lc;
    const float* Ap1 = A + (size_t)(row0 + lr + 64) * K + lc;
    const float* Bp0 = B + (size_t)(col0 + lr) * K + lc;
    const float* Bp1 = B + (size_t)(col0 + lr + 64) * K + lc;

    float acc[2][8][4];
#pragma unroll
    for (int mi = 0; mi < 2; mi++)
#pragma unroll
        for (int ni = 0; ni < 8; ni++)
#pragma unroll
            for (int r = 0; r < 4; r++) acc[mi][ni][r] = 0.f;

    float4 fa0 = *(const float4*)(Ap0);
    float4 fa1 = *(const float4*)(Ap1);
    float4 fb0 = *(const float4*)(Bp0);
    float4 fb1 = *(const float4*)(Bp1);

    for (int k0 = 0; k0 < K; k0 += GBK) {
        *(float4*)&As[lr * GST + lc]        = fa0;
        *(float4*)&As[(lr + 64) * GST + lc] = fa1;
        *(float4*)&Bs[lr * GST + lc]        = fb0;
        *(float4*)&Bs[(lr + 64) * GST + lc] = fb1;
        __syncthreads();

        if (k0 + GBK < K) {
            fa0 = *(const float4*)(Ap0 + k0 + GBK);
            fa1 = *(const float4*)(Ap1 + k0 + GBK);
            fb0 = *(const float4*)(Bp0 + k0 + GBK);
            fb1 = *(const float4*)(Bp1 + k0 + GBK);
        }

#pragma unroll
        for (int ks = 0; ks < 2; ks++) {
            const int kk = ks * 8 + tig;

            unsigned ahi[2][4], alo[2][4];
#pragma unroll
            for (int mi = 0; mi < 2; mi++) {
                int rb = (wm + mi * 16 + gid) * GST + kk;
                float x0 = As[rb];
                float x1 = As[rb + 8 * GST];
                float x2 = As[rb + 4];
                float x3 = As[rb + 8 * GST + 4];
                ahi[mi][0] = f2tf(x0); alo[mi][0] = f2tf(x0 - __uint_as_float(ahi[mi][0]));
                ahi[mi][1] = f2tf(x1); alo[mi][1] = f2tf(x1 - __uint_as_float(ahi[mi][1]));
                ahi[mi][2] = f2tf(x2); alo[mi][2] = f2tf(x2 - __uint_as_float(ahi[mi][2]));
                ahi[mi][3] = f2tf(x3); alo[mi][3] = f2tf(x3 - __uint_as_float(ahi[mi][3]));
            }

            unsigned bhi[8][2], blo[8][2];
#pragma unroll
            for (int ni = 0; ni < 8; ni++) {
                int rb = (wn + ni * 8 + gid) * GST + kk;
                float y0 = Bs[rb];
                float y1 = Bs[rb + 4];
                bhi[ni][0] = f2tf(y0); blo[ni][0] = f2tf(y0 - __uint_as_float(bhi[ni][0]));
                bhi[ni][1] = f2tf(y1); blo[ni][1] = f2tf(y1 - __uint_as_float(bhi[ni][1]));
            }

#pragma unroll
            for (int mi = 0; mi < 2; mi++)
#pragma unroll
                for (int ni = 0; ni < 8; ni++) {
                    mma_tf32(acc[mi][ni], ahi[mi], bhi[ni]);
                    mma_tf32(acc[mi][ni], ahi[mi], blo[ni]);
                    mma_tf32(acc[mi][ni], alo[mi], bhi[ni]);
                }
        }
        __syncthreads();
    }

#pragma unroll
    for (int mi = 0; mi < 2; mi++)
#pragma unroll
        for (int ni = 0; ni < 8; ni++) {
            int r = row0 + wm + mi * 16 + gid;
            int c = col0 + wn + ni * 8 + (tig << 1);
            *(float2*)&C[(size_t)r * N + c]       = make_float2(acc[mi][ni][0], acc[mi][ni][1]);
            *(float2*)&C[(size_t)(r + 8) * N + c] = make_float2(acc[mi][ni][2], acc[mi][ni][3]);
        }
}

// ---------------------------------------------------------------------------
// RoPE-3D (unchanged)
// ---------------------------------------------------------------------------
__global__ void rope_kernel(float* __restrict__ qkv,
                            const int* __restrict__ p_gh,
                            const int* __restrict__ p_gw) {
    int idx = blockIdx.x * blockDim.x + threadIdx.x;
    const int TOTAL = ROWS * 20 * 48;
    if (idx >= TOTAL) return;

    int pair = idx % 48;
    int head = (idx / 48) % 20;
    int row = idx / (48 * 20);
    int n = row % SEQ;

    int H = p_gh ? *p_gh : 16;
    int W = p_gw ? *p_gw : 16;
    int w = n % W;
    int h = (n / W) % H;
    int t = n / (W * H);

    int axis = pair / 16;
    int i = pair % 16;
    float pos = (float)(axis == 0 ? t : (axis == 1 ? h : w));

    float freq = powf(10000.f, -(float)i / 16.f);
    float ang = pos * freq;
    float s, c;
    sincosf(ang, &s, &c);

    int coloff = (head < 16) ? head * HDIM : (1536 + (head - 16) * HDIM);
    size_t base = (size_t)row * QKV_OUT + coloff + axis * 32 + 2 * i;
    float x0 = qkv[base];
    float x1 = qkv[base + 1];
    qkv[base] = x0 * c - x1 * s;
    qkv[base + 1] = x0 * s + x1 * c;
}

// ---------------------------------------------------------------------------
// Tensor-core flash attention (3xTF32 for S=QK^T and O=PV).
// Block: 256 threads = 8 warps; Q tile = 128 rows (16 per warp); K/V tile 64.
// Q/K/V staged in smem as (hi,lo) float2 pairs -> mainloop is LDS.64 + HMMA.
// Smem stride 100 float2 (== 4 mod 16) -> conflict-free fragment loads.
// ---------------------------------------------------------------------------
#define AQT 128
#define AKT 64
#define AST 100   // float2 stride per row
#define ATT_SMEM ((AQT + AKT + AKT) * AST * (int)sizeof(float2))   // 204800 B

__global__ __launch_bounds__(256, 1) void attn_mma(const float* __restrict__ qkv,
                                                   float* __restrict__ out) {
    extern __shared__ float2 sm[];
    float2* Q2 = sm;                    // [AQT][AST]
    float2* K2 = Q2 + AQT * AST;        // [AKT][AST]
    float2* V2 = K2 + AKT * AST;        // [AKT][AST]

    const int b = blockIdx.z;
    const int hh = blockIdx.y;
    const int g = hh >> 2;
    const int q0 = blockIdx.x * AQT;

    const int tid = threadIdx.x;
    const int lane = tid & 31;
    const int warp = tid >> 5;
    const int gid = lane >> 2;
    const int tig = lane & 3;
    const int wq = warp * 16;           // warp's q-row offset in tile

    const float scale = rsqrtf((float)HDIM);

    // ---- stage Q (convert once, scaled) ----
    for (int idx = tid; idx < AQT * (HDIM / 4); idx += 256) {
        int row = idx / (HDIM / 4);
        int c4 = (idx % (HDIM / 4)) * 4;
        const float* src = qkv + ((size_t)(b * SEQ + q0 + row)) * QKV_OUT + hh * HDIM + c4;
        float4 v = *(const float4*)src;
        float xs[4] = {v.x * scale, v.y * scale, v.z * scale, v.w * scale};
#pragma unroll
        for (int j = 0; j < 4; j++) {
            unsigned hi = f2tf(xs[j]);
            float lo = xs[j] - __uint_as_float(hi);
            Q2[row * AST + c4 + j] = make_float2(__uint_as_float(hi), __uint_as_float(f2tf(lo)));
        }
    }

    // accumulators
    float o[12][4];
#pragma unroll
    for (int ni = 0; ni < 12; ni++)
#pragma unroll
        for (int r = 0; r < 4; r++) o[ni][r] = 0.f;
    float m0 = -3.0e38f, m1 = -3.0e38f;
    float l0 = 0.f, l1 = 0.f;

    for (int kt = 0; kt < SEQ / AKT; kt++) {
        __syncthreads();
        // ---- stage K/V tile (convert to hi/lo) ----
        for (int idx = tid; idx < AKT * (HDIM / 4); idx += 256) {
            int row = idx / (HDIM / 4);
            int c4 = (idx % (HDIM / 4)) * 4;
            const float* src = qkv + ((size_t)(b * SEQ + kt * AKT + row)) * QKV_OUT + 1536 + g * HDIM + c4;
            float4 kv = *(const float4*)src;
            float4 vv = *(const float4*)(src + 384);
            float ka[4] = {kv.x, kv.y, kv.z, kv.w};
            float va[4] = {vv.x, vv.y, vv.z, vv.w};
#pragma unroll
            for (int j = 0; j < 4; j++) {
                unsigned khi = f2tf(ka[j]);
                K2[row * AST + c4 + j] = make_float2(__uint_as_float(khi),
                                                    __uint_as_float(f2tf(ka[j] - __uint_as_float(khi))));
                unsigned vhi = f2tf(va[j]);
                V2[row * AST + c4 + j] = make_float2(__uint_as_float(vhi),
                                                    __uint_as_float(f2tf(va[j] - __uint_as_float(vhi))));
            }
        }
        __syncthreads();

        // ---- S = Q K^T   (m16 x n64 x k96 per warp, 3xTF32) ----
        float sacc[8][4];
#pragma unroll
        for (int ni = 0; ni < 8; ni++)
#pragma unroll
            for (int r = 0; r < 4; r++) sacc[ni][r] = 0.f;

#pragma unroll
        for (int ks = 0; ks < HDIM / 8; ks++) {
            const float2* qr0 = Q2 + (wq + gid) * AST + ks * 8 + tig;
            const float2* qr1 = Q2 + (wq + gid + 8) * AST + ks * 8 + tig;
            float2 a0 = qr0[0], a2 = qr0[4];
            float2 a1 = qr1[0], a3 = qr1[4];
            unsigned ahi[4] = {__float_as_uint(a0.x), __float_as_uint(a1.x),
                               __float_as_uint(a2.x), __float_as_uint(a3.x)};
            unsigned alo[4] = {__float_as_uint(a0.y), __float_as_uint(a1.y),
                               __float_as_uint(a2.y), __float_as_uint(a3.y)};
#pragma unroll
            for (int ni = 0; ni < 8; ni++) {
                const float2* kr = K2 + (ni * 8 + gid) * AST + ks * 8 + tig;
                float2 b0 = kr[0], b1 = kr[4];
                unsigned bhi[2] = {__float_as_uint(b0.x), __float_as_uint(b1.x)};
                unsigned blo[2] = {__float_as_uint(b0.y), __float_as_uint(b1.y)};
                mma_tf32(sacc[ni], ahi, bhi);
                mma_tf32(sacc[ni], ahi, blo);
                mma_tf32(sacc[ni], alo, bhi);
            }
        }

        // ---- online softmax on fragments ----
        float tmax0 = -3.0e38f, tmax1 = -3.0e38f;
#pragma unroll
        for (int ni = 0; ni < 8; ni++) {
            tmax0 = fmaxf(tmax0, fmaxf(sacc[ni][0], sacc[ni][1]));
            tmax1 = fmaxf(tmax1, fmaxf(sacc[ni][2], sacc[ni][3]));
        }
        tmax0 = fmaxf(tmax0, __shfl_xor_sync(0xffffffffu, tmax0, 1));
        tmax0 = fmaxf(tmax0, __shfl_xor_sync(0xffffffffu, tmax0, 2));
        tmax1 = fmaxf(tmax1, __shfl_xor_sync(0xffffffffu, tmax1, 1));
        tmax1 = fmaxf(tmax1, __shfl_xor_sync(0xffffffffu, tmax1, 2));

        float mn0 = fmaxf(m0, tmax0);
        float mn1 = fmaxf(m1, tmax1);
        float corr0 = __expf(m0 - mn0);
        float corr1 = __expf(m1 - mn1);
        m0 = mn0; m1 = mn1;

        float sum0 = 0.f, sum1 = 0.f;
#pragma unroll
        for (int ni = 0; ni < 8; ni++) {
            float p0 = __expf(sacc[ni][0] - m0);
            float p1 = __expf(sacc[ni][1] - m0);
            float p2 = __expf(sacc[ni][2] - m1);
            float p3 = __expf(sacc[ni][3] - m1);
            sacc[ni][0] = p0; sacc[ni][1] = p1; sacc[ni][2] = p2; sacc[ni][3] = p3;
            sum0 += p0 + p1; sum1 += p2 + p3;
        }
        l0 = l0 * corr0 + sum0;       // per-thread partial; reduced at the end
        l1 = l1 * corr1 + sum1;

#pragma unroll
        for (int ni = 0; ni < 12; ni++) {
            o[ni][0] *= corr0; o[ni][1] *= corr0;
            o[ni][2] *= corr1; o[ni][3] *= corr1;
        }

        // ---- O += P V   (m16 x n96 x k64 per warp, 3xTF32) ----
        const int srcA = (lane & ~3) + (tig >> 1);
        const int srcB = srcA + 2;
        const bool odd = tig & 1;
#pragma unroll
        for (int ks = 0; ks < AKT / 8; ks++) {
            float c0 = sacc[ks][0], c1 = sacc[ks][1], c2 = sacc[ks][2], c3 = sacc[ks][3];
            float v0 = __shfl_sync(0xffffffffu, c0, srcA);
            float v1 = __shfl_sync(0xffffffffu, c1, srcA);
            float v2 = __shfl_sync(0xffffffffu, c2, srcA);
            float v3 = __shfl_sync(0xffffffffu, c3, srcA);
            float w0 = __shfl_sync(0xffffffffu, c0, srcB);
            float w1 = __shfl_sync(0xffffffffu, c1, srcB);
            float w2 = __shfl_sync(0xffffffffu, c2, srcB);
            float w3 = __shfl_sync(0xffffffffu, c3, srcB);
            float pa0 = odd ? v1 : v0;   // P[gid  ][8ks+tig]
            float pa1 = odd ? v3 : v2;   // P[gid+8][8ks+tig]
            float pa2 = odd ? w1 : w0;   // P[gid  ][8ks+tig+4]
            float pa3 = odd ? w3 : w2;   // P[gid+8][8ks+tig+4]

            unsigned phi[4], plo[4];
            phi[0] = f2tf(pa0); plo[0] = f2tf(pa0 - __uint_as_float(phi[0]));
            phi[1] = f2tf(pa1); plo[1] = f2tf(pa1 - __uint_as_float(phi[1]));
            phi[2] = f2tf(pa2); plo[2] = f2tf(pa2 - __uint_as_float(phi[2]));
            phi[3] = f2tf(pa3); plo[3] = f2tf(pa3 - __uint_as_float(phi[3]));

#pragma unroll
            for (int ni = 0; ni < 12; ni++) {
                float2 b0 = V2[(ks * 8 + tig) * AST + ni * 8 + gid];
                float2 b1 = V2[(ks * 8 + tig + 4) * AST + ni * 8 + gid];
                unsigned bhi[2] = {__float_as_uint(b0.x), __float_as_uint(b1.x)};
                unsigned blo[2] = {__float_as_uint(b0.y), __float_as_uint(b1.y)};
                mma_tf32(o[ni], phi, bhi);
                mma_tf32(o[ni], phi, blo);
                mma_tf32(o[ni], plo, bhi);
            }
        }
    }

    // ---- finalize: reduce l across the quad, normalize, write ----
    l0 += __shfl_xor_sync(0xffffffffu, l0, 1);
    l0 += __shfl_xor_sync(0xffffffffu, l0, 2);
    l1 += __shfl_xor_sync(0xffffffffu, l1, 1);
    l1 += __shfl_xor_sync(0xffffffffu, l1, 2);
    float inv0 = 1.f / l0;
    float inv1 = 1.f / l1;

    const int r0 = b * SEQ + q0 + wq + gid;
#pragma unroll
    for (int ni = 0; ni < 12; ni++) {
        int c = hh * HDIM + ni * 8 + (tig << 1);
        *(float2*)&out[(size_t)r0 * DMODEL + c] =
            make_float2(o[ni][0] * inv0, o[ni][1] * inv0);
        *(float2*)&out[(size_t)(r0 + 8) * DMODEL + c] =
            make_float2(o[ni][2] * inv1, o[ni][3] * inv1);
    }
}

// ---------------------------------------------------------------------------
extern "C" void kernel_launch(void* const* d_in, const int* in_sizes, int n_in,
                              void* d_out, int out_size) {
    const float* x = (const float*)d_in[0];
    const float* w_qkv = (const float*)d_in[1];
    const float* w_o = (const float*)d_in[2];
    const int* gh = (n_in >= 6) ? (const int*)d_in[4] : nullptr;
    const int* gw = (n_in >= 6) ? (const int*)d_in[5] : nullptr;
    float* out = (float*)d_out;

    float* qkv = nullptr;
    float* attn = nullptr;
    cudaGetSymbolAddress((void**)&qkv, g_qkv);
    cudaGetSymbolAddress((void**)&attn, g_attn);

    static int smem_set = 0;
    if (!smem_set) {
        cudaFuncSetAttribute(attn_mma, cudaFuncAttributeMaxDynamicSharedMemorySize, ATT_SMEM);
        smem_set = 1;
    }

    // 1) QKV projection
    {
        dim3 grid(QKV_OUT / GBN, ROWS / GBM);   // 18 x 32
        gemm_tf32<<<grid, 256>>>(x, w_qkv, qkv, ROWS, QKV_OUT, DMODEL);
    }

    // 2) RoPE
    {
        int total = ROWS * 20 * 48;
        rope_kernel<<<(total + 255) / 256, 256>>>(qkv, gh, gw);
    }

    // 3) Tensor-core flash attention
    {
        dim3 grid(SEQ / AQT, NHEADS, BATCH);    // 16 x 16 x 2
        attn_mma<<<grid, 256, ATT_SMEM>>>(qkv, attn);
    }

    // 4) Output projection
    {
        dim3 grid(DMODEL / GBN, ROWS / GBM);    // 12 x 32
        gemm_tf32<<<grid, 256>>>(attn, w_o, out, ROWS, DMODEL, DMODEL);
    }
}

// round 10
// speedup vs baseline: 2.3287x; 1.3638x over previous
#include <cuda_runtime.h>
#include <cuda_bf16.h>
#include <math.h>

// Problem constants (fixed by the dataset)
#define BATCH 2
#define SEQ 2048
#define DMODEL 1536
#define NHEADS 16
#define NGROUPS 4
#define HDIM 96
#define QKV_OUT 2304            // 16*96 + 2*4*96
#define ROWS (BATCH * SEQ)      // 4096

// Scratch (allocation-free rule: __device__ globals)
__device__ float g_qkv[(size_t)ROWS * QKV_OUT];   // ~37.7 MB
__device__ float g_attn[(size_t)ROWS * DMODEL];   // ~25.2 MB

// ---------------------------------------------------------------------------
// BF16 3-term split helpers.
// split2(a,b): returns uint2 where .x = bf16x2(hi(a),hi(b)) [a in low half]
// and .y = bf16x2(lo(a),lo(b)). hi = rn-bf16(x); lo = rn-bf16(x - hi) with
// the residual computed exactly in fp32.
// ---------------------------------------------------------------------------
__device__ __forceinline__ uint2 split2(float a, float b) {
    unsigned hi;
    asm("cvt.rn.bf16x2.f32 %0, %1, %2;" : "=r"(hi) : "f"(b), "f"(a));
    float ha = __uint_as_float(hi << 16);
    float hb = __uint_as_float(hi & 0xffff0000u);
    float ra = a - ha;
    float rb = b - hb;
    unsigned lo;
    asm("cvt.rn.bf16x2.f32 %0, %1, %2;" : "=r"(lo) : "f"(rb), "f"(ra));
    return make_uint2(hi, lo);
}

__device__ __forceinline__ void mma_bf16(float d[4],
                                         unsigned a0, unsigned a1, unsigned a2, unsigned a3,
                                         unsigned b0, unsigned b1) {
    asm volatile(
        "mma.sync.aligned.m16n8k16.row.col.f32.bf16.bf16.f32 "
        "{%0,%1,%2,%3}, {%4,%5,%6,%7}, {%8,%9}, {%0,%1,%2,%3};\n"
        : "+f"(d[0]), "+f"(d[1]), "+f"(d[2]), "+f"(d[3])
        : "r"(a0), "r"(a1), "r"(a2), "r"(a3), "r"(b0), "r"(b1));
}

// ---------------------------------------------------------------------------
// BF16x3 tensor-core GEMM: C[M,N] = A[M,K] * B[N,K]^T  (both K-major, "NT")
// Block 128x128, BK=32, 512 threads (16 warps, 4x4), warp tile 32x32.
// Smem: k-pair-major [16 pairs][128 rows + 4 pad] of uint2 (hi_pair, lo_pair).
// Row stride 132 (== 4 mod 16 in 8B units) -> conflict-free LDS.64 + STS.64.
// ---------------------------------------------------------------------------
#define GBM 128
#define GBN 128
#define GBK 32
#define GRS 132   // uint2 row stride per k-pair

__global__ __launch_bounds__(512, 1) void gemm_bf16x3(const float* __restrict__ A,
                                                      const float* __restrict__ B,
                                                      float* __restrict__ C,
                                                      int M, int N, int K) {
    __shared__ uint2 As[16 * GRS];   // 16896 B
    __shared__ uint2 Bs[16 * GRS];

    const int tid = threadIdx.x;
    const int lane = tid & 31;
    const int warp = tid >> 5;          // 0..15
    const int gid = lane >> 2;
    const int tig = lane & 3;
    const int wm = (warp >> 2) * 32;    // 0,32,64,96
    const int wn = (warp & 3) * 32;     // 0,32,64,96
    const int row0 = blockIdx.y * GBM;
    const int col0 = blockIdx.x * GBN;

    // loader mapping: row = tid&127 (consecutive lanes -> consecutive rows),
    // q = tid>>7 selects the 8-col chunk
    const int lrow = tid & 127;
    const int lq = tid >> 7;            // 0..3

    const float* Ap = A + (size_t)(row0 + lrow) * K + lq * 8;
    const float* Bp = B + (size_t)(col0 + lrow) * K + lq * 8;

    float acc[2][4][4];
#pragma unroll
    for (int mi = 0; mi < 2; mi++)
#pragma unroll
        for (int ni = 0; ni < 4; ni++)
#pragma unroll
            for (int r = 0; r < 4; r++) acc[mi][ni][r] = 0.f;

    float4 pa0 = *(const float4*)(Ap);
    float4 pa1 = *(const float4*)(Ap + 4);
    float4 pb0 = *(const float4*)(Bp);
    float4 pb1 = *(const float4*)(Bp + 4);

    for (int k0 = 0; k0 < K; k0 += GBK) {
        // convert + store staged tile (pairs j = lq*4 + jj)
        {
            int jb = lq * 4;
            As[(jb + 0) * GRS + lrow] = split2(pa0.x, pa0.y);
            As[(jb + 1) * GRS + lrow] = split2(pa0.z, pa0.w);
            As[(jb + 2) * GRS + lrow] = split2(pa1.x, pa1.y);
            As[(jb + 3) * GRS + lrow] = split2(pa1.z, pa1.w);
            Bs[(jb + 0) * GRS + lrow] = split2(pb0.x, pb0.y);
            Bs[(jb + 1) * GRS + lrow] = split2(pb0.z, pb0.w);
            Bs[(jb + 2) * GRS + lrow] = split2(pb1.x, pb1.y);
            Bs[(jb + 3) * GRS + lrow] = split2(pb1.z, pb1.w);
        }
        __syncthreads();

        if (k0 + GBK < K) {
            pa0 = *(const float4*)(Ap + k0 + GBK);
            pa1 = *(const float4*)(Ap + k0 + GBK + 4);
            pb0 = *(const float4*)(Bp + k0 + GBK);
            pb1 = *(const float4*)(Bp + k0 + GBK + 4);
        }

#pragma unroll
        for (int ks = 0; ks < 2; ks++) {
            const int j0 = ks * 8 + tig;
            const int j1 = j0 + 4;

            uint2 a[2][4];
#pragma unroll
            for (int mi = 0; mi < 2; mi++) {
                int r = wm + mi * 16 + gid;
                a[mi][0] = As[j0 * GRS + r];
                a[mi][1] = As[j0 * GRS + r + 8];
                a[mi][2] = As[j1 * GRS + r];
                a[mi][3] = As[j1 * GRS + r + 8];
            }
            uint2 b[4][2];
#pragma unroll
            for (int ni = 0; ni < 4; ni++) {
                int c = wn + ni * 8 + gid;
                b[ni][0] = Bs[j0 * GRS + c];
                b[ni][1] = Bs[j1 * GRS + c];
            }
#pragma unroll
            for (int mi = 0; mi < 2; mi++)
#pragma unroll
                for (int ni = 0; ni < 4; ni++) {
                    mma_bf16(acc[mi][ni], a[mi][0].x, a[mi][1].x, a[mi][2].x, a[mi][3].x,
                             b[ni][0].x, b[ni][1].x);
                    mma_bf16(acc[mi][ni], a[mi][0].x, a[mi][1].x, a[mi][2].x, a[mi][3].x,
                             b[ni][0].y, b[ni][1].y);
                    mma_bf16(acc[mi][ni], a[mi][0].y, a[mi][1].y, a[mi][2].y, a[mi][3].y,
                             b[ni][0].x, b[ni][1].x);
                }
        }
        __syncthreads();
    }

#pragma unroll
    for (int mi = 0; mi < 2; mi++)
#pragma unroll
        for (int ni = 0; ni < 4; ni++) {
            int r = row0 + wm + mi * 16 + gid;
            int c = col0 + wn + ni * 8 + (tig << 1);
            *(float2*)&C[(size_t)r * N + c]       = make_float2(acc[mi][ni][0], acc[mi][ni][1]);
            *(float2*)&C[(size_t)(r + 8) * N + c] = make_float2(acc[mi][ni][2], acc[mi][ni][3]);
        }
}

// ---------------------------------------------------------------------------
// RoPE-3D (unchanged)
// ---------------------------------------------------------------------------
__global__ void rope_kernel(float* __restrict__ qkv,
                            const int* __restrict__ p_gh,
                            const int* __restrict__ p_gw) {
    int idx = blockIdx.x * blockDim.x + threadIdx.x;
    const int TOTAL = ROWS * 20 * 48;
    if (idx >= TOTAL) return;

    int pair = idx % 48;
    int head = (idx / 48) % 20;
    int row = idx / (48 * 20);
    int n = row % SEQ;

    int H = p_gh ? *p_gh : 16;
    int W = p_gw ? *p_gw : 16;
    int w = n % W;
    int h = (n / W) % H;
    int t = n / (W * H);

    int axis = pair / 16;
    int i = pair % 16;
    float pos = (float)(axis == 0 ? t : (axis == 1 ? h : w));

    float freq = powf(10000.f, -(float)i / 16.f);
    float ang = pos * freq;
    float s, c;
    sincosf(ang, &s, &c);

    int coloff = (head < 16) ? head * HDIM : (1536 + (head - 16) * HDIM);
    size_t base = (size_t)row * QKV_OUT + coloff + axis * 32 + 2 * i;
    float x0 = qkv[base];
    float x1 = qkv[base + 1];
    qkv[base] = x0 * c - x1 * s;
    qkv[base + 1] = x0 * s + x1 * c;
}

// ---------------------------------------------------------------------------
// BF16x3 tensor-core flash attention.
// Block: 256 threads = 8 warps; Q tile = 128 rows (16/warp); K/V tile 64.
// Smem (uint2 = packed hi/lo bf16x2 pairs):
//   Qs: dim-pair-major  [48][128+4]  (stride 132, ==4 mod 16)
//   Ks: dim-pair-major  [48][64+4]   (stride 68)
//   Vs: key-pair rows   [32][96+4]   (stride 100)
// P fragments for PV come straight from S accumulators (k16 col pairing
// matches the C-fragment pairing) -> no shuffles.
// ---------------------------------------------------------------------------
#define AQT 128
#define AKT 64
#define QRS 132
#define KRS 68
#define VRS 100
#define ATT_SMEM ((48 * QRS + 48 * KRS + 32 * VRS) * (int)sizeof(uint2))  // 102400 B

__global__ __launch_bounds__(256, 1) void attn_bf16(const float* __restrict__ qkv,
                                                    float* __restrict__ out) {
    extern __shared__ uint2 sm[];
    uint2* Qs = sm;                 // [48][QRS]
    uint2* Ks = Qs + 48 * QRS;      // [48][KRS]
    uint2* Vs = Ks + 48 * KRS;      // [32][VRS]

    const int b = blockIdx.z;
    const int hh = blockIdx.y;
    const int g = hh >> 2;
    const int q0 = blockIdx.x * AQT;

    const int tid = threadIdx.x;
    const int lane = tid & 31;
    const int warp = tid >> 5;
    const int gid = lane >> 2;
    const int tig = lane & 3;
    const int wq = warp * 16;

    const float scale = rsqrtf((float)HDIM);

    // ---- stage Q (convert once, scaled): thread -> row=tid&127, half=tid>>7
    {
        const int row = tid & 127;
        const int half = tid >> 7;           // dims half*48 .. +47
        const float* src = qkv + ((size_t)(b * SEQ + q0 + row)) * QKV_OUT + hh * HDIM + half * 48;
#pragma unroll
        for (int i = 0; i < 12; i++) {
            float4 v = *(const float4*)(src + i * 4);
            int j = half * 24 + i * 2;       // dim-pair index
            Qs[j * QRS + row]       = split2(v.x * scale, v.y * scale);
            Qs[(j + 1) * QRS + row] = split2(v.z * scale, v.w * scale);
        }
    }

    float o[12][4];
#pragma unroll
    for (int ni = 0; ni < 12; ni++)
#pragma unroll
        for (int r = 0; r < 4; r++) o[ni][r] = 0.f;
    float m0 = -3.0e38f, m1 = -3.0e38f;
    float l0 = 0.f, l1 = 0.f;

    for (int kt = 0; kt < SEQ / AKT; kt++) {
        __syncthreads();
        // ---- stage K: thread -> key=tid&63, third=tid>>6 (dims third*24..+23)
        {
            const int key = tid & 63;
            const int third = tid >> 6;
            const float* src = qkv + ((size_t)(b * SEQ + kt * AKT + key)) * QKV_OUT
                               + 1536 + g * HDIM + third * 24;
#pragma unroll
            for (int i = 0; i < 6; i++) {
                float4 v = *(const float4*)(src + i * 4);
                int j = third * 12 + i * 2;
                Ks[j * KRS + key]       = split2(v.x, v.y);
                Ks[(j + 1) * KRS + key] = split2(v.z, v.w);
            }
        }
        // ---- stage V (pairs along keys): thread -> kp=tid&31, oct=tid>>5
        {
            const int kp = tid & 31;
            const int oct = tid >> 5;        // dims oct*12..+11
            const float* srcA = qkv + ((size_t)(b * SEQ + kt * AKT + 2 * kp)) * QKV_OUT
                                + 1536 + NGROUPS * HDIM + g * HDIM + oct * 12;
            const float* srcB = srcA + QKV_OUT;
#pragma unroll
            for (int i = 0; i < 3; i++) {
                float4 va = *(const float4*)(srcA + i * 4);
                float4 vb = *(const float4*)(srcB + i * 4);
                uint2 e0 = split2(va.x, vb.x);
                uint2 e1 = split2(va.y, vb.y);
                uint2 e2 = split2(va.z, vb.z);
                uint2 e3 = split2(va.w, vb.w);
                uint2* dst = &Vs[kp * VRS + oct * 12 + i * 4];
                *(uint4*)(dst)     = make_uint4(e0.x, e0.y, e1.x, e1.y);
                *(uint4*)(dst + 2) = make_uint4(e2.x, e2.y, e3.x, e3.y);
            }
        }
        __syncthreads();

        // ---- S = Q K^T  (m16 x n64 x k96 per warp, bf16x3, k16 steps) ----
        float sacc[8][4];
#pragma unroll
        for (int ni = 0; ni < 8; ni++)
#pragma unroll
            for (int r = 0; r < 4; r++) sacc[ni][r] = 0.f;

#pragma unroll
        for (int ks = 0; ks < HDIM / 16; ks++) {
            const int j0 = ks * 8 + tig;
            const int j1 = j0 + 4;
            uint2 a0 = Qs[j0 * QRS + wq + gid];
            uint2 a1 = Qs[j0 * QRS + wq + gid + 8];
            uint2 a2 = Qs[j1 * QRS + wq + gid];
            uint2 a3 = Qs[j1 * QRS + wq + gid + 8];
#pragma unroll
            for (int ni = 0; ni < 8; ni++) {
                uint2 b0 = Ks[j0 * KRS + ni * 8 + gid];
                uint2 b1 = Ks[j1 * KRS + ni * 8 + gid];
                mma_bf16(sacc[ni], a0.x, a1.x, a2.x, a3.x, b0.x, b1.x);
                mma_bf16(sacc[ni], a0.x, a1.x, a2.x, a3.x, b0.y, b1.y);
                mma_bf16(sacc[ni], a0.y, a1.y, a2.y, a3.y, b0.x, b1.x);
            }
        }

        // ---- online softmax on fragments ----
        float tmax0 = -3.0e38f, tmax1 = -3.0e38f;
#pragma unroll
        for (int ni = 0; ni < 8; ni++) {
            tmax0 = fmaxf(tmax0, fmaxf(sacc[ni][0], sacc[ni][1]));
            tmax1 = fmaxf(tmax1, fmaxf(sacc[ni][2], sacc[ni][3]));
        }
        tmax0 = fmaxf(tmax0, __shfl_xor_sync(0xffffffffu, tmax0, 1));
        tmax0 = fmaxf(tmax0, __shfl_xor_sync(0xffffffffu, tmax0, 2));
        tmax1 = fmaxf(tmax1, __shfl_xor_sync(0xffffffffu, tmax1, 1));
        tmax1 = fmaxf(tmax1, __shfl_xor_sync(0xffffffffu, tmax1, 2));

        float mn0 = fmaxf(m0, tmax0);
        float mn1 = fmaxf(m1, tmax1);
        float corr0 = __expf(m0 - mn0);
        float corr1 = __expf(m1 - mn1);
        m0 = mn0; m1 = mn1;

        float sum0 = 0.f, sum1 = 0.f;
#pragma unroll
        for (int ni = 0; ni < 8; ni++) {
            float p0 = __expf(sacc[ni][0] - m0);
            float p1 = __expf(sacc[ni][1] - m0);
            float p2 = __expf(sacc[ni][2] - m1);
            float p3 = __expf(sacc[ni][3] - m1);
            sacc[ni][0] = p0; sacc[ni][1] = p1; sacc[ni][2] = p2; sacc[ni][3] = p3;
            sum0 += p0 + p1; sum1 += p2 + p3;
        }
        l0 = l0 * corr0 + sum0;
        l1 = l1 * corr1 + sum1;

#pragma unroll
        for (int ni = 0; ni < 12; ni++) {
            o[ni][0] *= corr0; o[ni][1] *= corr0;
            o[ni][2] *= corr1; o[ni][3] *= corr1;
        }

        // ---- O += P V  (m16 x n96 x k64, bf16x3; P direct from sacc) ----
#pragma unroll
        for (int ks = 0; ks < AKT / 16; ks++) {
            uint2 p0 = split2(sacc[2 * ks][0],     sacc[2 * ks][1]);
            uint2 p1 = split2(sacc[2 * ks][2],     sacc[2 * ks][3]);
            uint2 p2 = split2(sacc[2 * ks + 1][0], sacc[2 * ks + 1][1]);
            uint2 p3 = split2(sacc[2 * ks + 1][2], sacc[2 * ks + 1][3]);
            const int j0 = ks * 8 + tig;
            const int j1 = j0 + 4;
#pragma unroll
            for (int ni = 0; ni < 12; ni++) {
                uint2 b0 = Vs[j0 * VRS + ni * 8 + gid];
                uint2 b1 = Vs[j1 * VRS + ni * 8 + gid];
                mma_bf16(o[ni], p0.x, p1.x, p2.x, p3.x, b0.x, b1.x);
                mma_bf16(o[ni], p0.x, p1.x, p2.x, p3.x, b0.y, b1.y);
                mma_bf16(o[ni], p0.y, p1.y, p2.y, p3.y, b0.x, b1.x);
            }
        }
    }

    // ---- finalize: reduce l across the quad, normalize, write ----
    l0 += __shfl_xor_sync(0xffffffffu, l0, 1);
    l0 += __shfl_xor_sync(0xffffffffu, l0, 2);
    l1 += __shfl_xor_sync(0xffffffffu, l1, 1);
    l1 += __shfl_xor_sync(0xffffffffu, l1, 2);
    float inv0 = 1.f / l0;
    float inv1 = 1.f / l1;

    const int r0 = b * SEQ + q0 + wq + gid;
#pragma unroll
    for (int ni = 0; ni < 12; ni++) {
        int c = hh * HDIM + ni * 8 + (tig << 1);
        *(float2*)&out[(size_t)r0 * DMODEL + c] =
            make_float2(o[ni][0] * inv0, o[ni][1] * inv0);
        *(float2*)&out[(size_t)(r0 + 8) * DMODEL + c] =
            make_float2(o[ni][2] * inv1, o[ni][3] * inv1);
    }
}

// ---------------------------------------------------------------------------
extern "C" void kernel_launch(void* const* d_in, const int* in_sizes, int n_in,
                              void* d_out, int out_size) {
    const float* x = (const float*)d_in[0];
    const float* w_qkv = (const float*)d_in[1];
    const float* w_o = (const float*)d_in[2];
    const int* gh = (n_in >= 6) ? (const int*)d_in[4] : nullptr;
    const int* gw = (n_in >= 6) ? (const int*)d_in[5] : nullptr;
    float* out = (float*)d_out;

    float* qkv = nullptr;
    float* attn = nullptr;
    cudaGetSymbolAddress((void**)&qkv, g_qkv);
    cudaGetSymbolAddress((void**)&attn, g_attn);

    static int smem_set = 0;
    if (!smem_set) {
        cudaFuncSetAttribute(attn_bf16, cudaFuncAttributeMaxDynamicSharedMemorySize, ATT_SMEM);
        smem_set = 1;
    }

    // 1) QKV projection
    {
        dim3 grid(QKV_OUT / GBN, ROWS / GBM);   // 18 x 32
        gemm_bf16x3<<<grid, 512>>>(x, w_qkv, qkv, ROWS, QKV_OUT, DMODEL);
    }

    // 2) RoPE
    {
        int total = ROWS * 20 * 48;
        rope_kernel<<<(total + 255) / 256, 256>>>(qkv, gh, gw);
    }

    // 3) Tensor-core flash attention
    {
        dim3 grid(SEQ / AQT, NHEADS, BATCH);    // 16 x 16 x 2
        attn_bf16<<<grid, 256, ATT_SMEM>>>(qkv, attn);
    }

    // 4) Output projection
    {
        dim3 grid(DMODEL / GBN, ROWS / GBM);    // 12 x 32
        gemm_bf16x3<<<grid, 512>>>(attn, w_o, out, ROWS, DMODEL, DMODEL);
    }
}

// round 13
// speedup vs baseline: 2.5002x; 1.0737x over previous
#include <cuda_runtime.h>
#include <cuda_bf16.h>
#include <stdint.h>
#include <math.h>

// Problem constants (fixed by the dataset)
#define BATCH 2
#define SEQ 2048
#define DMODEL 1536
#define NHEADS 16
#define NGROUPS 4
#define HDIM 96
#define QKV_OUT 2304            // 16*96 + 2*4*96
#define ROWS (BATCH * SEQ)      // 4096

// Scratch (allocation-free rule: __device__ globals)
__device__ float g_qkv[(size_t)ROWS * QKV_OUT];   // ~37.7 MB
__device__ float g_attn[(size_t)ROWS * DMODEL];   // ~25.2 MB
// bf16 hi/lo planes for GEMM operands (A reused for x and attn; B for weights)
__device__ __nv_bfloat16 c_ahi[(size_t)ROWS * DMODEL];
__device__ __nv_bfloat16 c_alo[(size_t)ROWS * DMODEL];
__device__ __nv_bfloat16 c_bhi[(size_t)QKV_OUT * DMODEL];
__device__ __nv_bfloat16 c_blo[(size_t)QKV_OUT * DMODEL];

// ---------------------------------------------------------------------------
// BF16 3-term split helpers.
// split2(a,b): .x = bf16x2 with hi(a) in LOW half, hi(b) in HIGH half;
// .y = same packing of the rn-bf16 residuals (computed exactly in fp32).
// ---------------------------------------------------------------------------
__device__ __forceinline__ uint2 split2(float a, float b) {
    unsigned hi;
    asm("cvt.rn.bf16x2.f32 %0, %1, %2;" : "=r"(hi) : "f"(b), "f"(a));
    float ha = __uint_as_float(hi << 16);
    float hb = __uint_as_float(hi & 0xffff0000u);
    float ra = a - ha;
    float rb = b - hb;
    unsigned lo;
    asm("cvt.rn.bf16x2.f32 %0, %1, %2;" : "=r"(lo) : "f"(rb), "f"(ra));
    return make_uint2(hi, lo);
}

__device__ __forceinline__ void mma_bf16(float d[4],
                                         unsigned a0, unsigned a1, unsigned a2, unsigned a3,
                                         unsigned b0, unsigned b1) {
    asm volatile(
        "mma.sync.aligned.m16n8k16.row.col.f32.bf16.bf16.f32 "
        "{%0,%1,%2,%3}, {%4,%5,%6,%7}, {%8,%9}, {%0,%1,%2,%3};\n"
        : "+f"(d[0]), "+f"(d[1]), "+f"(d[2]), "+f"(d[3])
        : "r"(a0), "r"(a1), "r"(a2), "r"(a3), "r"(b0), "r"(b1));
}

__device__ __forceinline__ void ldsm4(uint32_t addr, unsigned& r0, unsigned& r1,
                                      unsigned& r2, unsigned& r3) {
    asm volatile("ldmatrix.sync.aligned.m8n8.x4.shared.b16 {%0,%1,%2,%3}, [%4];"
                 : "=r"(r0), "=r"(r1), "=r"(r2), "=r"(r3) : "r"(addr));
}

// ---------------------------------------------------------------------------
// Elementwise split: fp32 -> (hi bf16 plane, lo bf16 plane). 4 floats/thread.
// ---------------------------------------------------------------------------
__global__ void convert_split(const float* __restrict__ src,
                              __nv_bfloat16* __restrict__ hi,
                              __nv_bfloat16* __restrict__ lo, int n4) {
    int idx = blockIdx.x * blockDim.x + threadIdx.x;
    if (idx >= n4) return;
    float4 v = ((const float4*)src)[idx];
    uint2 s0 = split2(v.x, v.y);
    uint2 s1 = split2(v.z, v.w);
    ((uint2*)hi)[idx] = make_uint2(s0.x, s1.x);
    ((uint2*)lo)[idx] = make_uint2(s0.y, s1.y);
}

// ---------------------------------------------------------------------------
// Pre-split bf16x3 GEMM: C[M,N] = A[M,K] * B[N,K]^T with A/B given as
// separate hi/lo bf16 planes (K-major).
// Block 128x128, BK=32, 512 threads (16 warps 4x4, warp tile 32x32).
// 3-stage cp.async pipeline; smem tiles [128 rows][32 bf16] @ stride 80B
// (conflict-free for both cp.async stores and ldmatrix 8-row phases).
// ---------------------------------------------------------------------------
#define PBK 32
#define PROWB 80                         // bytes per smem row
#define PTILE (128 * PROWB)              // 10240 B per tile
#define PSTAGE (4 * PTILE)               // Ahi,Alo,Bhi,Blo = 40960 B
#define PNSTAGE 3
#define PG_SMEM (PNSTAGE * PSTAGE)       // 122880 B

__global__ __launch_bounds__(512, 1) void gemm_pre(const __nv_bfloat16* __restrict__ Ahi,
                                                   const __nv_bfloat16* __restrict__ Alo,
                                                   const __nv_bfloat16* __restrict__ Bhi,
                                                   const __nv_bfloat16* __restrict__ Blo,
                                                   float* __restrict__ C,
                                                   int M, int N, int K) {
    extern __shared__ __align__(128) char smem[];
    const uint32_t sbase = (uint32_t)__cvta_generic_to_shared(smem);

    const int tid = threadIdx.x;
    const int lane = tid & 31;
    const int warp = tid >> 5;           // 0..15
    const int gid = lane >> 2;
    const int tig = lane & 3;
    const int wm = (warp >> 2) * 32;
    const int wn = (warp & 3) * 32;
    const int row0 = blockIdx.y * 128;
    const int col0 = blockIdx.x * 128;

    // ---- loader mapping: tile t = tid>>7 (0:Ahi 1:Alo 2:Bhi 3:Blo), row=tid&127
    const int lt = tid >> 7;
    const int lrow = tid & 127;
    const __nv_bfloat16* gsrc;
    if (lt == 0)      gsrc = Ahi + (size_t)(row0 + lrow) * K;
    else if (lt == 1) gsrc = Alo + (size_t)(row0 + lrow) * K;
    else if (lt == 2) gsrc = Bhi + (size_t)(col0 + lrow) * K;
    else              gsrc = Blo + (size_t)(col0 + lrow) * K;
    const uint32_t ldst = (uint32_t)lt * PTILE + (uint32_t)lrow * PROWB;

    // ---- fragment smem offsets (within a stage) ----
    // A (row-major m16k16): matrix m=lane>>3 -> row wm + (m&1)*8 + (lane&7), col (m>>1)*16
    const uint32_t aoff = (uint32_t)(wm + (((lane >> 3) & 1) << 3) + (lane & 7)) * PROWB
                          + (((uint32_t)(lane >> 4) & 1) << 4);
    // B (n-major rows): matrix m -> row wn + p*16 + ((m>>1)&1)*8 + (lane&7), col (m&1)*16
    const uint32_t boff = (uint32_t)(wn + (((lane >> 4) & 1) << 3) + (lane & 7)) * PROWB
                          + (((uint32_t)(lane >> 3) & 1) << 4);

    float acc[2][4][4];
#pragma unroll
    for (int mi = 0; mi < 2; mi++)
#pragma unroll
        for (int ni = 0; ni < 4; ni++)
#pragma unroll
            for (int r = 0; r < 4; r++) acc[mi][ni][r] = 0.f;

    const int nch = K / PBK;             // 48

    // ---- prologue: stages 0 and 1 ----
#pragma unroll
    for (int p = 0; p < 2; p++) {
        uint32_t dst = sbase + (uint32_t)p * PSTAGE + ldst;
        const __nv_bfloat16* src = gsrc + (size_t)p * PBK;
#pragma unroll
        for (int s = 0; s < 4; s++)
            asm volatile("cp.async.cg.shared.global [%0], [%1], 16;"
                         :: "r"(dst + s * 16), "l"(src + s * 8) : "memory");
        asm volatile("cp.async.commit_group;" ::: "memory");
    }

    for (int c = 0; c < nch; c++) {
        if (c < nch - 1)
            asm volatile("cp.async.wait_group 1;" ::: "memory");
        else
            asm volatile("cp.async.wait_group 0;" ::: "memory");
        __syncthreads();

        // issue chunk c+2 into stage (c+2)%3 (its last reader finished at c-1)
        if (c + 2 < nch) {
            uint32_t dst = sbase + (uint32_t)((c + 2) % PNSTAGE) * PSTAGE + ldst;
            const __nv_bfloat16* src = gsrc + (size_t)(c + 2) * PBK;
#pragma unroll
            for (int s = 0; s < 4; s++)
                asm volatile("cp.async.cg.shared.global [%0], [%1], 16;"
                             :: "r"(dst + s * 16), "l"(src + s * 8) : "memory");
            asm volatile("cp.async.commit_group;" ::: "memory");
        }

        const uint32_t sa = sbase + (uint32_t)(c % PNSTAGE) * PSTAGE;
#pragma unroll
        for (int ks = 0; ks < 2; ks++) {
            const uint32_t kb = (uint32_t)ks * 32;
            unsigned ah[4], al[4], bh[8], bl[8];
            ldsm4(sa + aoff + kb, ah[0], ah[1], ah[2], ah[3]);
            ldsm4(sa + PTILE + aoff + kb, al[0], al[1], al[2], al[3]);
            ldsm4(sa + 2 * PTILE + boff + kb, bh[0], bh[1], bh[2], bh[3]);
            ldsm4(sa + 2 * PTILE + boff + 16 * PROWB + kb, bh[4], bh[5], bh[6], bh[7]);
            ldsm4(sa + 3 * PTILE + boff + kb, bl[0], bl[1], bl[2], bl[3]);
            ldsm4(sa + 3 * PTILE + boff + 16 * PROWB + kb, bl[4], bl[5], bl[6], bl[7]);

#pragma unroll
            for (int mi = 0; mi < 2; mi++) {
                unsigned* a = (mi == 0) ? ah : al;   // placeholder; replaced below
            }
            // hi*hi + hi*lo + lo*hi for each (mi, ni)
#pragma unroll
            for (int mi = 0; mi < 2; mi++) {
                // A fragment for this mi: rows wm+mi*16.. -> use ah/al with offset?
            }
            // NOTE: A fragments above cover rows wm..wm+15 only (one m16 tile).
            // Second m-tile (rows wm+16..wm+31) loaded here:
            unsigned ah2[4], al2[4];
            ldsm4(sa + aoff + 16 * PROWB + kb, ah2[0], ah2[1], ah2[2], ah2[3]);
            ldsm4(sa + PTILE + aoff + 16 * PROWB + kb, al2[0], al2[1], al2[2], al2[3]);

#pragma unroll
            for (int ni = 0; ni < 4; ni++) {
                unsigned b0h = bh[ni * 2], b1h = bh[ni * 2 + 1];
                unsigned b0l = bl[ni * 2], b1l = bl[ni * 2 + 1];
                mma_bf16(acc[0][ni], ah[0], ah[1], ah[2], ah[3], b0h, b1h);
                mma_bf16(acc[0][ni], ah[0], ah[1], ah[2], ah[3], b0l, b1l);
                mma_bf16(acc[0][ni], al[0], al[1], al[2], al[3], b0h, b1h);
                mma_bf16(acc[1][ni], ah2[0], ah2[1], ah2[2], ah2[3], b0h, b1h);
                mma_bf16(acc[1][ni], ah2[0], ah2[1], ah2[2], ah2[3], b0l, b1l);
                mma_bf16(acc[1][ni], al2[0], al2[1], al2[2], al2[3], b0h, b1h);
            }
        }
        __syncthreads();
    }

    // ---- epilogue ----
#pragma unroll
    for (int mi = 0; mi < 2; mi++)
#pragma unroll
        for (int ni = 0; ni < 4; ni++) {
            int r = row0 + wm + mi * 16 + gid;
            int cc = col0 + wn + ni * 8 + (tig << 1);
            *(float2*)&C[(size_t)r * N + cc]       = make_float2(acc[mi][ni][0], acc[mi][ni][1]);
            *(float2*)&C[(size_t)(r + 8) * N + cc] = make_float2(acc[mi][ni][2], acc[mi][ni][3]);
        }
}

// ---------------------------------------------------------------------------
// RoPE-3D (unchanged)
// ---------------------------------------------------------------------------
__global__ void rope_kernel(float* __restrict__ qkv,
                            const int* __restrict__ p_gh,
                            const int* __restrict__ p_gw) {
    int idx = blockIdx.x * blockDim.x + threadIdx.x;
    const int TOTAL = ROWS * 20 * 48;
    if (idx >= TOTAL) return;

    int pair = idx % 48;
    int head = (idx / 48) % 20;
    int row = idx / (48 * 20);
    int n = row % SEQ;

    int H = p_gh ? *p_gh : 16;
    int W = p_gw ? *p_gw : 16;
    int w = n % W;
    int h = (n / W) % H;
    int t = n / (W * H);

    int axis = pair / 16;
    int i = pair % 16;
    float pos = (float)(axis == 0 ? t : (axis == 1 ? h : w));

    float freq = powf(10000.f, -(float)i / 16.f);
    float ang = pos * freq;
    float s, c;
    sincosf(ang, &s, &c);

    int coloff = (head < 16) ? head * HDIM : (1536 + (head - 16) * HDIM);
    size_t base = (size_t)row * QKV_OUT + coloff + axis * 32 + 2 * i;
    float x0 = qkv[base];
    float x1 = qkv[base + 1];
    qkv[base] = x0 * c - x1 * s;
    qkv[base + 1] = x0 * s + x1 * c;
}

// ---------------------------------------------------------------------------
// BF16x3 tensor-core flash attention (unchanged from R10 — passing @ ~620us).
// ---------------------------------------------------------------------------
#define AQT 128
#define AKT 64
#define QRS 132
#define KRS 68
#define VRS 100
#define ATT_SMEM ((48 * QRS + 48 * KRS + 32 * VRS) * (int)sizeof(uint2))  // 102400 B

__global__ __launch_bounds__(256, 1) void attn_bf16(const float* __restrict__ qkv,
                                                    float* __restrict__ out) {
    extern __shared__ uint2 sm[];
    uint2* Qs = sm;                 // [48][QRS]
    uint2* Ks = Qs + 48 * QRS;      // [48][KRS]
    uint2* Vs = Ks + 48 * KRS;      // [32][VRS]

    const int b = blockIdx.z;
    const int hh = blockIdx.y;
    const int g = hh >> 2;
    const int q0 = blockIdx.x * AQT;

    const int tid = threadIdx.x;
    const int lane = tid & 31;
    const int warp = tid >> 5;
    const int gid = lane >> 2;
    const int tig = lane & 3;
    const int wq = warp * 16;

    const float scale = rsqrtf((float)HDIM);

    // ---- stage Q (convert once, scaled)
    {
        const int row = tid & 127;
        const int half = tid >> 7;
        const float* src = qkv + ((size_t)(b * SEQ + q0 + row)) * QKV_OUT + hh * HDIM + half * 48;
#pragma unroll
        for (int i = 0; i < 12; i++) {
            float4 v = *(const float4*)(src + i * 4);
            int j = half * 24 + i * 2;
            Qs[j * QRS + row]       = split2(v.x * scale, v.y * scale);
            Qs[(j + 1) * QRS + row] = split2(v.z * scale, v.w * scale);
        }
    }

    float o[12][4];
#pragma unroll
    for (int ni = 0; ni < 12; ni++)
#pragma unroll
        for (int r = 0; r < 4; r++) o[ni][r] = 0.f;
    float m0 = -3.0e38f, m1 = -3.0e38f;
    float l0 = 0.f, l1 = 0.f;

    for (int kt = 0; kt < SEQ / AKT; kt++) {
        __syncthreads();
        {
            const int key = tid & 63;
            const int third = tid >> 6;
            const float* src = qkv + ((size_t)(b * SEQ + kt * AKT + key)) * QKV_OUT
                               + 1536 + g * HDIM + third * 24;
#pragma unroll
            for (int i = 0; i < 6; i++) {
                float4 v = *(const float4*)(src + i * 4);
                int j = third * 12 + i * 2;
                Ks[j * KRS + key]       = split2(v.x, v.y);
                Ks[(j + 1) * KRS + key] = split2(v.z, v.w);
            }
        }
        {
            const int kp = tid & 31;
            const int oct = tid >> 5;
            const float* srcA = qkv + ((size_t)(b * SEQ + kt * AKT + 2 * kp)) * QKV_OUT
                                + 1536 + NGROUPS * HDIM + g * HDIM + oct * 12;
            const float* srcB = srcA + QKV_OUT;
#pragma unroll
            for (int i = 0; i < 3; i++) {
                float4 va = *(const float4*)(srcA + i * 4);
                float4 vb = *(const float4*)(srcB + i * 4);
                uint2 e0 = split2(va.x, vb.x);
                uint2 e1 = split2(va.y, vb.y);
                uint2 e2 = split2(va.z, vb.z);
                uint2 e3 = split2(va.w, vb.w);
                uint2* dst = &Vs[kp * VRS + oct * 12 + i * 4];
                *(uint4*)(dst)     = make_uint4(e0.x, e0.y, e1.x, e1.y);
                *(uint4*)(dst + 2) = make_uint4(e2.x, e2.y, e3.x, e3.y);
            }
        }
        __syncthreads();

        // ---- S = Q K^T
        float sacc[8][4];
#pragma unroll
        for (int ni = 0; ni < 8; ni++)
#pragma unroll
            for (int r = 0; r < 4; r++) sacc[ni][r] = 0.f;

#pragma unroll
        for (int ks = 0; ks < HDIM / 16; ks++) {
            const int j0 = ks * 8 + tig;
            const int j1 = j0 + 4;
            uint2 a0 = Qs[j0 * QRS + wq + gid];
            uint2 a1 = Qs[j0 * QRS + wq + gid + 8];
            uint2 a2 = Qs[j1 * QRS + wq + gid];
            uint2 a3 = Qs[j1 * QRS + wq + gid + 8];
#pragma unroll
            for (int ni = 0; ni < 8; ni++) {
                uint2 b0 = Ks[j0 * KRS + ni * 8 + gid];
                uint2 b1 = Ks[j1 * KRS + ni * 8 + gid];
                mma_bf16(sacc[ni], a0.x, a1.x, a2.x, a3.x, b0.x, b1.x);
                mma_bf16(sacc[ni], a0.x, a1.x, a2.x, a3.x, b0.y, b1.y);
                mma_bf16(sacc[ni], a0.y, a1.y, a2.y, a3.y, b0.x, b1.x);
            }
        }

        // ---- online softmax
        float tmax0 = -3.0e38f, tmax1 = -3.0e38f;
#pragma unroll
        for (int ni = 0; ni < 8; ni++) {
            tmax0 = fmaxf(tmax0, fmaxf(sacc[ni][0], sacc[ni][1]));
            tmax1 = fmaxf(tmax1, fmaxf(sacc[ni][2], sacc[ni][3]));
        }
        tmax0 = fmaxf(tmax0, __shfl_xor_sync(0xffffffffu, tmax0, 1));
        tmax0 = fmaxf(tmax0, __shfl_xor_sync(0xffffffffu, tmax0, 2));
        tmax1 = fmaxf(tmax1, __shfl_xor_sync(0xffffffffu, tmax1, 1));
        tmax1 = fmaxf(tmax1, __shfl_xor_sync(0xffffffffu, tmax1, 2));

        float mn0 = fmaxf(m0, tmax0);
        float mn1 = fmaxf(m1, tmax1);
        float corr0 = __expf(m0 - mn0);
        float corr1 = __expf(m1 - mn1);
        m0 = mn0; m1 = mn1;

        float sum0 = 0.f, sum1 = 0.f;
#pragma unroll
        for (int ni = 0; ni < 8; ni++) {
            float p0 = __expf(sacc[ni][0] - m0);
            float p1 = __expf(sacc[ni][1] - m0);
            float p2 = __expf(sacc[ni][2] - m1);
            float p3 = __expf(sacc[ni][3] - m1);
            sacc[ni][0] = p0; sacc[ni][1] = p1; sacc[ni][2] = p2; sacc[ni][3] = p3;
            sum0 += p0 + p1; sum1 += p2 + p3;
        }
        l0 = l0 * corr0 + sum0;
        l1 = l1 * corr1 + sum1;

#pragma unroll
        for (int ni = 0; ni < 12; ni++) {
            o[ni][0] *= corr0; o[ni][1] *= corr0;
            o[ni][2] *= corr1; o[ni][3] *= corr1;
        }

        // ---- O += P V
#pragma unroll
        for (int ks = 0; ks < AKT / 16; ks++) {
            uint2 p0 = split2(sacc[2 * ks][0],     sacc[2 * ks][1]);
            uint2 p1 = split2(sacc[2 * ks][2],     sacc[2 * ks][3]);
            uint2 p2 = split2(sacc[2 * ks + 1][0], sacc[2 * ks + 1][1]);
            uint2 p3 = split2(sacc[2 * ks + 1][2], sacc[2 * ks + 1][3]);
            const int j0 = ks * 8 + tig;
            const int j1 = j0 + 4;
#pragma unroll
            for (int ni = 0; ni < 12; ni++) {
                uint2 b0 = Vs[j0 * VRS + ni * 8 + gid];
                uint2 b1 = Vs[j1 * VRS + ni * 8 + gid];
                mma_bf16(o[ni], p0.x, p1.x, p2.x, p3.x, b0.x, b1.x);
                mma_bf16(o[ni], p0.x, p1.x, p2.x, p3.x, b0.y, b1.y);
                mma_bf16(o[ni], p0.y, p1.y, p2.y, p3.y, b0.x, b1.x);
            }
        }
    }

    // ---- finalize
    l0 += __shfl_xor_sync(0xffffffffu, l0, 1);
    l0 += __shfl_xor_sync(0xffffffffu, l0, 2);
    l1 += __shfl_xor_sync(0xffffffffu, l1, 1);
    l1 += __shfl_xor_sync(0xffffffffu, l1, 2);
    float inv0 = 1.f / l0;
    float inv1 = 1.f / l1;

    const int r0 = b * SEQ + q0 + wq + gid;
#pragma unroll
    for (int ni = 0; ni < 12; ni++) {
        int c = hh * HDIM + ni * 8 + (tig << 1);
        *(float2*)&out[(size_t)r0 * DMODEL + c] =
            make_float2(o[ni][0] * inv0, o[ni][1] * inv0);
        *(float2*)&out[(size_t)(r0 + 8) * DMODEL + c] =
            make_float2(o[ni][2] * inv1, o[ni][3] * inv1);
    }
}

// ---------------------------------------------------------------------------
extern "C" void kernel_launch(void* const* d_in, const int* in_sizes, int n_in,
                              void* d_out, int out_size) {
    const float* x = (const float*)d_in[0];
    const float* w_qkv = (const float*)d_in[1];
    const float* w_o = (const float*)d_in[2];
    const int* gh = (n_in >= 6) ? (const int*)d_in[4] : nullptr;
    const int* gw = (n_in >= 6) ? (const int*)d_in[5] : nullptr;
    float* out = (float*)d_out;

    float* qkv = nullptr;
    float* attn = nullptr;
    __nv_bfloat16 *ahi, *alo, *bhi, *blo;
    cudaGetSymbolAddress((void**)&qkv, g_qkv);
    cudaGetSymbolAddress((void**)&attn, g_attn);
    cudaGetSymbolAddress((void**)&ahi, c_ahi);
    cudaGetSymbolAddress((void**)&alo, c_alo);
    cudaGetSymbolAddress((void**)&bhi, c_bhi);
    cudaGetSymbolAddress((void**)&blo, c_blo);

    static int smem_set = 0;
    if (!smem_set) {
        cudaFuncSetAttribute(attn_bf16, cudaFuncAttributeMaxDynamicSharedMemorySize, ATT_SMEM);
        cudaFuncSetAttribute(gemm_pre, cudaFuncAttributeMaxDynamicSharedMemorySize, PG_SMEM);
        smem_set = 1;
    }

    // 1) split x and w_qkv into bf16 hi/lo planes
    {
        int n4 = ROWS * DMODEL / 4;
        convert_split<<<(n4 + 255) / 256, 256>>>(x, ahi, alo, n4);
        int m4 = QKV_OUT * DMODEL / 4;
        convert_split<<<(m4 + 255) / 256, 256>>>(w_qkv, bhi, blo, m4);
    }

    // 2) QKV projection: [4096,1536] x [2304,1536]^T
    {
        dim3 grid(QKV_OUT / 128, ROWS / 128);   // 18 x 32
        gemm_pre<<<grid, 512, PG_SMEM>>>(ahi, alo, bhi, blo, qkv, ROWS, QKV_OUT, DMODEL);
    }

    // 3) RoPE
    {
        int total = ROWS * 20 * 48;
        rope_kernel<<<(total + 255) / 256, 256>>>(qkv, gh, gw);
    }

    // 4) Tensor-core flash attention
    {
        dim3 grid(SEQ / AQT, NHEADS, BATCH);    // 16 x 16 x 2
        attn_bf16<<<grid, 256, ATT_SMEM>>>(qkv, attn);
    }

    // 5) split attn output and w_o
    {
        int n4 = ROWS * DMODEL / 4;
        convert_split<<<(n4 + 255) / 256, 256>>>(attn, ahi, alo, n4);
        int m4 = DMODEL * DMODEL / 4;
        convert_split<<<(m4 + 255) / 256, 256>>>(w_o, bhi, blo, m4);
    }

    // 6) Output projection: [4096,1536] x [1536,1536]^T
    {
        dim3 grid(DMODEL / 128, ROWS / 128);    // 12 x 32
        gemm_pre<<<grid, 512, PG_SMEM>>>(ahi, alo, bhi, blo, out, ROWS, DMODEL, DMODEL);
    }
}

// round 14
// speedup vs baseline: 3.2715x; 1.3085x over previous
#include <cuda_runtime.h>
#include <cuda_bf16.h>
#include <stdint.h>
#include <math.h>

// Problem constants (fixed by the dataset)
#define BATCH 2
#define SEQ 2048
#define DMODEL 1536
#define NHEADS 16
#define NGROUPS 4
#define HDIM 96
#define QKV_OUT 2304            // 16*96 + 2*4*96
#define ROWS (BATCH * SEQ)      // 4096

// Scratch (allocation-free rule: __device__ globals)
__device__ float g_qkv[(size_t)ROWS * QKV_OUT];   // ~37.7 MB
__device__ float g_attn[(size_t)ROWS * DMODEL];   // ~25.2 MB
// bf16 hi/lo planes for GEMM operands (A reused for x and attn; B for weights)
__device__ __nv_bfloat16 c_ahi[(size_t)ROWS * DMODEL];
__device__ __nv_bfloat16 c_alo[(size_t)ROWS * DMODEL];
__device__ __nv_bfloat16 c_bhi[(size_t)QKV_OUT * DMODEL];
__device__ __nv_bfloat16 c_blo[(size_t)QKV_OUT * DMODEL];

// ---------------------------------------------------------------------------
// BF16 3-term split helpers (GEMM path).
// ---------------------------------------------------------------------------
__device__ __forceinline__ uint2 split2(float a, float b) {
    unsigned hi;
    asm("cvt.rn.bf16x2.f32 %0, %1, %2;" : "=r"(hi) : "f"(b), "f"(a));
    float ha = __uint_as_float(hi << 16);
    float hb = __uint_as_float(hi & 0xffff0000u);
    float ra = a - ha;
    float rb = b - hb;
    unsigned lo;
    asm("cvt.rn.bf16x2.f32 %0, %1, %2;" : "=r"(lo) : "f"(rb), "f"(ra));
    return make_uint2(hi, lo);
}

// fp16x2 pack (a in LOW half = earlier element)
__device__ __forceinline__ unsigned pack_f16(float a, float b) {
    unsigned r;
    asm("cvt.rn.f16x2.f32 %0, %1, %2;" : "=r"(r) : "f"(b), "f"(a));
    return r;
}

__device__ __forceinline__ void mma_bf16(float d[4],
                                         unsigned a0, unsigned a1, unsigned a2, unsigned a3,
                                         unsigned b0, unsigned b1) {
    asm volatile(
        "mma.sync.aligned.m16n8k16.row.col.f32.bf16.bf16.f32 "
        "{%0,%1,%2,%3}, {%4,%5,%6,%7}, {%8,%9}, {%0,%1,%2,%3};\n"
        : "+f"(d[0]), "+f"(d[1]), "+f"(d[2]), "+f"(d[3])
        : "r"(a0), "r"(a1), "r"(a2), "r"(a3), "r"(b0), "r"(b1));
}

__device__ __forceinline__ void mma_f16(float d[4],
                                        unsigned a0, unsigned a1, unsigned a2, unsigned a3,
                                        unsigned b0, unsigned b1) {
    asm volatile(
        "mma.sync.aligned.m16n8k16.row.col.f32.f16.f16.f32 "
        "{%0,%1,%2,%3}, {%4,%5,%6,%7}, {%8,%9}, {%0,%1,%2,%3};\n"
        : "+f"(d[0]), "+f"(d[1]), "+f"(d[2]), "+f"(d[3])
        : "r"(a0), "r"(a1), "r"(a2), "r"(a3), "r"(b0), "r"(b1));
}

__device__ __forceinline__ void ldsm4(uint32_t addr, unsigned& r0, unsigned& r1,
                                      unsigned& r2, unsigned& r3) {
    asm volatile("ldmatrix.sync.aligned.m8n8.x4.shared.b16 {%0,%1,%2,%3}, [%4];"
                 : "=r"(r0), "=r"(r1), "=r"(r2), "=r"(r3) : "r"(addr));
}

// ---------------------------------------------------------------------------
// Elementwise split: fp32 -> (hi bf16 plane, lo bf16 plane). 4 floats/thread.
// ---------------------------------------------------------------------------
__global__ void convert_split(const float* __restrict__ src,
                              __nv_bfloat16* __restrict__ hi,
                              __nv_bfloat16* __restrict__ lo, int n4) {
    int idx = blockIdx.x * blockDim.x + threadIdx.x;
    if (idx >= n4) return;
    float4 v = ((const float4*)src)[idx];
    uint2 s0 = split2(v.x, v.y);
    uint2 s1 = split2(v.z, v.w);
    ((uint2*)hi)[idx] = make_uint2(s0.x, s1.x);
    ((uint2*)lo)[idx] = make_uint2(s0.y, s1.y);
}

// ---------------------------------------------------------------------------
// Pre-split bf16x3 GEMM (unchanged from R13 — passing).
// ---------------------------------------------------------------------------
#define PBK 32
#define PROWB 80                         // bytes per smem row
#define PTILE (128 * PROWB)              // 10240 B per tile
#define PSTAGE (4 * PTILE)               // Ahi,Alo,Bhi,Blo = 40960 B
#define PNSTAGE 3
#define PG_SMEM (PNSTAGE * PSTAGE)       // 122880 B

__global__ __launch_bounds__(512, 1) void gemm_pre(const __nv_bfloat16* __restrict__ Ahi,
                                                   const __nv_bfloat16* __restrict__ Alo,
                                                   const __nv_bfloat16* __restrict__ Bhi,
                                                   const __nv_bfloat16* __restrict__ Blo,
                                                   float* __restrict__ C,
                                                   int M, int N, int K) {
    extern __shared__ __align__(128) char smem[];
    const uint32_t sbase = (uint32_t)__cvta_generic_to_shared(smem);

    const int tid = threadIdx.x;
    const int lane = tid & 31;
    const int warp = tid >> 5;           // 0..15
    const int gid = lane >> 2;
    const int tig = lane & 3;
    const int wm = (warp >> 2) * 32;
    const int wn = (warp & 3) * 32;
    const int row0 = blockIdx.y * 128;
    const int col0 = blockIdx.x * 128;

    const int lt = tid >> 7;
    const int lrow = tid & 127;
    const __nv_bfloat16* gsrc;
    if (lt == 0)      gsrc = Ahi + (size_t)(row0 + lrow) * K;
    else if (lt == 1) gsrc = Alo + (size_t)(row0 + lrow) * K;
    else if (lt == 2) gsrc = Bhi + (size_t)(col0 + lrow) * K;
    else              gsrc = Blo + (size_t)(col0 + lrow) * K;
    const uint32_t ldst = (uint32_t)lt * PTILE + (uint32_t)lrow * PROWB;

    const uint32_t aoff = (uint32_t)(wm + (((lane >> 3) & 1) << 3) + (lane & 7)) * PROWB
                          + (((uint32_t)(lane >> 4) & 1) << 4);
    const uint32_t boff = (uint32_t)(wn + (((lane >> 4) & 1) << 3) + (lane & 7)) * PROWB
                          + (((uint32_t)(lane >> 3) & 1) << 4);

    float acc[2][4][4];
#pragma unroll
    for (int mi = 0; mi < 2; mi++)
#pragma unroll
        for (int ni = 0; ni < 4; ni++)
#pragma unroll
            for (int r = 0; r < 4; r++) acc[mi][ni][r] = 0.f;

    const int nch = K / PBK;             // 48

#pragma unroll
    for (int p = 0; p < 2; p++) {
        uint32_t dst = sbase + (uint32_t)p * PSTAGE + ldst;
        const __nv_bfloat16* src = gsrc + (size_t)p * PBK;
#pragma unroll
        for (int s = 0; s < 4; s++)
            asm volatile("cp.async.cg.shared.global [%0], [%1], 16;"
                         :: "r"(dst + s * 16), "l"(src + s * 8) : "memory");
        asm volatile("cp.async.commit_group;" ::: "memory");
    }

    for (int c = 0; c < nch; c++) {
        if (c < nch - 1)
            asm volatile("cp.async.wait_group 1;" ::: "memory");
        else
            asm volatile("cp.async.wait_group 0;" ::: "memory");
        __syncthreads();

        if (c + 2 < nch) {
            uint32_t dst = sbase + (uint32_t)((c + 2) % PNSTAGE) * PSTAGE + ldst;
            const __nv_bfloat16* src = gsrc + (size_t)(c + 2) * PBK;
#pragma unroll
            for (int s = 0; s < 4; s++)
                asm volatile("cp.async.cg.shared.global [%0], [%1], 16;"
                             :: "r"(dst + s * 16), "l"(src + s * 8) : "memory");
            asm volatile("cp.async.commit_group;" ::: "memory");
        }

        const uint32_t sa = sbase + (uint32_t)(c % PNSTAGE) * PSTAGE;
#pragma unroll
        for (int ks = 0; ks < 2; ks++) {
            const uint32_t kb = (uint32_t)ks * 32;
            unsigned ah[4], al[4], bh[8], bl[8];
            ldsm4(sa + aoff + kb, ah[0], ah[1], ah[2], ah[3]);
            ldsm4(sa + PTILE + aoff + kb, al[0], al[1], al[2], al[3]);
            ldsm4(sa + 2 * PTILE + boff + kb, bh[0], bh[1], bh[2], bh[3]);
            ldsm4(sa + 2 * PTILE + boff + 16 * PROWB + kb, bh[4], bh[5], bh[6], bh[7]);
            ldsm4(sa + 3 * PTILE + boff + kb, bl[0], bl[1], bl[2], bl[3]);
            ldsm4(sa + 3 * PTILE + boff + 16 * PROWB + kb, bl[4], bl[5], bl[6], bl[7]);

            unsigned ah2[4], al2[4];
            ldsm4(sa + aoff + 16 * PROWB + kb, ah2[0], ah2[1], ah2[2], ah2[3]);
            ldsm4(sa + PTILE + aoff + 16 * PROWB + kb, al2[0], al2[1], al2[2], al2[3]);

#pragma unroll
            for (int ni = 0; ni < 4; ni++) {
                unsigned b0h = bh[ni * 2], b1h = bh[ni * 2 + 1];
                unsigned b0l = bl[ni * 2], b1l = bl[ni * 2 + 1];
                mma_bf16(acc[0][ni], ah[0], ah[1], ah[2], ah[3], b0h, b1h);
                mma_bf16(acc[0][ni], ah[0], ah[1], ah[2], ah[3], b0l, b1l);
                mma_bf16(acc[0][ni], al[0], al[1], al[2], al[3], b0h, b1h);
                mma_bf16(acc[1][ni], ah2[0], ah2[1], ah2[2], ah2[3], b0h, b1h);
                mma_bf16(acc[1][ni], ah2[0], ah2[1], ah2[2], ah2[3], b0l, b1l);
                mma_bf16(acc[1][ni], al2[0], al2[1], al2[2], al2[3], b0h, b1h);
            }
        }
        __syncthreads();
    }

#pragma unroll
    for (int mi = 0; mi < 2; mi++)
#pragma unroll
        for (int ni = 0; ni < 4; ni++) {
            int r = row0 + wm + mi * 16 + gid;
            int cc = col0 + wn + ni * 8 + (tig << 1);
            *(float2*)&C[(size_t)r * N + cc]       = make_float2(acc[mi][ni][0], acc[mi][ni][1]);
            *(float2*)&C[(size_t)(r + 8) * N + cc] = make_float2(acc[mi][ni][2], acc[mi][ni][3]);
        }
}

// ---------------------------------------------------------------------------
// RoPE-3D (unchanged)
// ---------------------------------------------------------------------------
__global__ void rope_kernel(float* __restrict__ qkv,
                            const int* __restrict__ p_gh,
                            const int* __restrict__ p_gw) {
    int idx = blockIdx.x * blockDim.x + threadIdx.x;
    const int TOTAL = ROWS * 20 * 48;
    if (idx >= TOTAL) return;

    int pair = idx % 48;
    int head = (idx / 48) % 20;
    int row = idx / (48 * 20);
    int n = row % SEQ;

    int H = p_gh ? *p_gh : 16;
    int W = p_gw ? *p_gw : 16;
    int w = n % W;
    int h = (n / W) % H;
    int t = n / (W * H);

    int axis = pair / 16;
    int i = pair % 16;
    float pos = (float)(axis == 0 ? t : (axis == 1 ? h : w));

    float freq = powf(10000.f, -(float)i / 16.f);
    float ang = pos * freq;
    float s, c;
    sincosf(ang, &s, &c);

    int coloff = (head < 16) ? head * HDIM : (1536 + (head - 16) * HDIM);
    size_t base = (size_t)row * QKV_OUT + coloff + axis * 32 + 2 * i;
    float x0 = qkv[base];
    float x1 = qkv[base + 1];
    qkv[base] = x0 * c - x1 * s;
    qkv[base + 1] = x0 * s + x1 * c;
}

// ---------------------------------------------------------------------------
// FP16 single-term tensor-core flash attention.
// Block: 256 threads = 8 warps; Q tile 128 rows (16/warp); K/V tile 64.
// Smem planes are fp16x2-packed uints:
//   Qs [48 dim-pairs][136]  Ks [48 dim-pairs][72]  Vs [32 key-pairs][104]
// Strides 136/72/104 are ==8 mod 32 -> fragment LDS.32 phases hit
// tig*8+gid = all 32 distinct banks (conflict-free).
// 1 HMMA per fragment position (was 3), half the staging work.
// ---------------------------------------------------------------------------
#define AQT 128
#define AKT 64
#define QRS 136
#define KRS 72
#define VRS 104
#define ATT_SMEM ((48 * QRS + 48 * KRS + 32 * VRS) * (int)sizeof(unsigned))  // 53248 B

__global__ __launch_bounds__(256) void attn_f16(const float* __restrict__ qkv,
                                                float* __restrict__ out) {
    extern __shared__ unsigned smu[];
    unsigned* Qs = smu;                 // [48][QRS]
    unsigned* Ks = Qs + 48 * QRS;       // [48][KRS]
    unsigned* Vs = Ks + 48 * KRS;       // [32][VRS]

    const int b = blockIdx.z;
    const int hh = blockIdx.y;
    const int g = hh >> 2;
    const int q0 = blockIdx.x * AQT;

    const int tid = threadIdx.x;
    const int lane = tid & 31;
    const int warp = tid >> 5;
    const int gid = lane >> 2;
    const int tig = lane & 3;
    const int wq = warp * 16;

    const float scale = rsqrtf((float)HDIM);

    // ---- stage Q (convert once, scaled): row=tid&127, half=tid>>7
    {
        const int row = tid & 127;
        const int half = tid >> 7;
        const float* src = qkv + ((size_t)(b * SEQ + q0 + row)) * QKV_OUT + hh * HDIM + half * 48;
#pragma unroll
        for (int i = 0; i < 12; i++) {
            float4 v = *(const float4*)(src + i * 4);
            int j = half * 24 + i * 2;
            Qs[j * QRS + row]       = pack_f16(v.x * scale, v.y * scale);
            Qs[(j + 1) * QRS + row] = pack_f16(v.z * scale, v.w * scale);
        }
    }

    float o[12][4];
#pragma unroll
    for (int ni = 0; ni < 12; ni++)
#pragma unroll
        for (int r = 0; r < 4; r++) o[ni][r] = 0.f;
    float m0 = -3.0e38f, m1 = -3.0e38f;
    float l0 = 0.f, l1 = 0.f;

    for (int kt = 0; kt < SEQ / AKT; kt++) {
        __syncthreads();
        // ---- stage K: key=tid&63, third=tid>>6 (dims third*24..+23)
        {
            const int key = tid & 63;
            const int third = tid >> 6;
            const float* src = qkv + ((size_t)(b * SEQ + kt * AKT + key)) * QKV_OUT
                               + 1536 + g * HDIM + third * 24;
#pragma unroll
            for (int i = 0; i < 6; i++) {
                float4 v = *(const float4*)(src + i * 4);
                int j = third * 12 + i * 2;
                Ks[j * KRS + key]       = pack_f16(v.x, v.y);
                Ks[(j + 1) * KRS + key] = pack_f16(v.z, v.w);
            }
        }
        // ---- stage V: kp=tid&31 (key pair), oct=tid>>5 (dims oct*12..+11)
        {
            const int kp = tid & 31;
            const int oct = tid >> 5;
            const float* srcA = qkv + ((size_t)(b * SEQ + kt * AKT + 2 * kp)) * QKV_OUT
                                + 1536 + NGROUPS * HDIM + g * HDIM + oct * 12;
            const float* srcB = srcA + QKV_OUT;
#pragma unroll
            for (int i = 0; i < 3; i++) {
                float4 va = *(const float4*)(srcA + i * 4);
                float4 vb = *(const float4*)(srcB + i * 4);
                unsigned* dst = &Vs[kp * VRS + oct * 12 + i * 4];
                *(uint4*)dst = make_uint4(pack_f16(va.x, vb.x), pack_f16(va.y, vb.y),
                                          pack_f16(va.z, vb.z), pack_f16(va.w, vb.w));
            }
        }
        __syncthreads();

        // ---- S = Q K^T  (m16 x n64 x k96 per warp, single fp16 term) ----
        float sacc[8][4];
#pragma unroll
        for (int ni = 0; ni < 8; ni++)
#pragma unroll
            for (int r = 0; r < 4; r++) sacc[ni][r] = 0.f;

#pragma unroll
        for (int ks = 0; ks < HDIM / 16; ks++) {
            const int j0 = ks * 8 + tig;
            const int j1 = j0 + 4;
            unsigned a0 = Qs[j0 * QRS + wq + gid];
            unsigned a1 = Qs[j0 * QRS + wq + gid + 8];
            unsigned a2 = Qs[j1 * QRS + wq + gid];
            unsigned a3 = Qs[j1 * QRS + wq + gid + 8];
#pragma unroll
            for (int ni = 0; ni < 8; ni++) {
                unsigned b0 = Ks[j0 * KRS + ni * 8 + gid];
                unsigned b1 = Ks[j1 * KRS + ni * 8 + gid];
                mma_f16(sacc[ni], a0, a1, a2, a3, b0, b1);
            }
        }

        // ---- online softmax ----
        float tmax0 = -3.0e38f, tmax1 = -3.0e38f;
#pragma unroll
        for (int ni = 0; ni < 8; ni++) {
            tmax0 = fmaxf(tmax0, fmaxf(sacc[ni][0], sacc[ni][1]));
            tmax1 = fmaxf(tmax1, fmaxf(sacc[ni][2], sacc[ni][3]));
        }
        tmax0 = fmaxf(tmax0, __shfl_xor_sync(0xffffffffu, tmax0, 1));
        tmax0 = fmaxf(tmax0, __shfl_xor_sync(0xffffffffu, tmax0, 2));
        tmax1 = fmaxf(tmax1, __shfl_xor_sync(0xffffffffu, tmax1, 1));
        tmax1 = fmaxf(tmax1, __shfl_xor_sync(0xffffffffu, tmax1, 2));

        float mn0 = fmaxf(m0, tmax0);
        float mn1 = fmaxf(m1, tmax1);
        float corr0 = __expf(m0 - mn0);
        float corr1 = __expf(m1 - mn1);
        m0 = mn0; m1 = mn1;

        float sum0 = 0.f, sum1 = 0.f;
#pragma unroll
        for (int ni = 0; ni < 8; ni++) {
            float p0 = __expf(sacc[ni][0] - m0);
            float p1 = __expf(sacc[ni][1] - m0);
            float p2 = __expf(sacc[ni][2] - m1);
            float p3 = __expf(sacc[ni][3] - m1);
            sacc[ni][0] = p0; sacc[ni][1] = p1; sacc[ni][2] = p2; sacc[ni][3] = p3;
            sum0 += p0 + p1; sum1 += p2 + p3;
        }
        l0 = l0 * corr0 + sum0;
        l1 = l1 * corr1 + sum1;

#pragma unroll
        for (int ni = 0; ni < 12; ni++) {
            o[ni][0] *= corr0; o[ni][1] *= corr0;
            o[ni][2] *= corr1; o[ni][3] *= corr1;
        }

        // ---- O += P V  (m16 x n96 x k64; P packed straight from sacc) ----
#pragma unroll
        for (int ks = 0; ks < AKT / 16; ks++) {
            unsigned p0 = pack_f16(sacc[2 * ks][0],     sacc[2 * ks][1]);
            unsigned p1 = pack_f16(sacc[2 * ks][2],     sacc[2 * ks][3]);
            unsigned p2 = pack_f16(sacc[2 * ks + 1][0], sacc[2 * ks + 1][1]);
            unsigned p3 = pack_f16(sacc[2 * ks + 1][2], sacc[2 * ks + 1][3]);
            const int j0 = ks * 8 + tig;
            const int j1 = j0 + 4;
#pragma unroll
            for (int ni = 0; ni < 12; ni++) {
                unsigned b0 = Vs[j0 * VRS + ni * 8 + gid];
                unsigned b1 = Vs[j1 * VRS + ni * 8 + gid];
                mma_f16(o[ni], p0, p1, p2, p3, b0, b1);
            }
        }
    }

    // ---- finalize ----
    l0 += __shfl_xor_sync(0xffffffffu, l0, 1);
    l0 += __shfl_xor_sync(0xffffffffu, l0, 2);
    l1 += __shfl_xor_sync(0xffffffffu, l1, 1);
    l1 += __shfl_xor_sync(0xffffffffu, l1, 2);
    float inv0 = 1.f / l0;
    float inv1 = 1.f / l1;

    const int r0 = b * SEQ + q0 + wq + gid;
#pragma unroll
    for (int ni = 0; ni < 12; ni++) {
        int c = hh * HDIM + ni * 8 + (tig << 1);
        *(float2*)&out[(size_t)r0 * DMODEL + c] =
            make_float2(o[ni][0] * inv0, o[ni][1] * inv0);
        *(float2*)&out[(size_t)(r0 + 8) * DMODEL + c] =
            make_float2(o[ni][2] * inv1, o[ni][3] * inv1);
    }
}

// ---------------------------------------------------------------------------
extern "C" void kernel_launch(void* const* d_in, const int* in_sizes, int n_in,
                              void* d_out, int out_size) {
    const float* x = (const float*)d_in[0];
    const float* w_qkv = (const float*)d_in[1];
    const float* w_o = (const float*)d_in[2];
    const int* gh = (n_in >= 6) ? (const int*)d_in[4] : nullptr;
    const int* gw = (n_in >= 6) ? (const int*)d_in[5] : nullptr;
    float* out = (float*)d_out;

    float* qkv = nullptr;
    float* attn = nullptr;
    __nv_bfloat16 *ahi, *alo, *bhi, *blo;
    cudaGetSymbolAddress((void**)&qkv, g_qkv);
    cudaGetSymbolAddress((void**)&attn, g_attn);
    cudaGetSymbolAddress((void**)&ahi, c_ahi);
    cudaGetSymbolAddress((void**)&alo, c_alo);
    cudaGetSymbolAddress((void**)&bhi, c_bhi);
    cudaGetSymbolAddress((void**)&blo, c_blo);

    static int smem_set = 0;
    if (!smem_set) {
        cudaFuncSetAttribute(attn_f16, cudaFuncAttributeMaxDynamicSharedMemorySize, ATT_SMEM);
        cudaFuncSetAttribute(gemm_pre, cudaFuncAttributeMaxDynamicSharedMemorySize, PG_SMEM);
        smem_set = 1;
    }

    // 1) split x and w_qkv into bf16 hi/lo planes
    {
        int n4 = ROWS * DMODEL / 4;
        convert_split<<<(n4 + 255) / 256, 256>>>(x, ahi, alo, n4);
        int m4 = QKV_OUT * DMODEL / 4;
        convert_split<<<(m4 + 255) / 256, 256>>>(w_qkv, bhi, blo, m4);
    }

    // 2) QKV projection: [4096,1536] x [2304,1536]^T
    {
        dim3 grid(QKV_OUT / 128, ROWS / 128);   // 18 x 32
        gemm_pre<<<grid, 512, PG_SMEM>>>(ahi, alo, bhi, blo, qkv, ROWS, QKV_OUT, DMODEL);
    }

    // 3) RoPE
    {
        int total = ROWS * 20 * 48;
        rope_kernel<<<(total + 255) / 256, 256>>>(qkv, gh, gw);
    }

    // 4) FP16 tensor-core flash attention
    {
        dim3 grid(SEQ / AQT, NHEADS, BATCH);    // 16 x 16 x 2
        attn_f16<<<grid, 256, ATT_SMEM>>>(qkv, attn);
    }

    // 5) split attn output and w_o
    {
        int n4 = ROWS * DMODEL / 4;
        convert_split<<<(n4 + 255) / 256, 256>>>(attn, ahi, alo, n4);
        int m4 = DMODEL * DMODEL / 4;
        convert_split<<<(m4 + 255) / 256, 256>>>(w_o, bhi, blo, m4);
    }

    // 6) Output projection: [4096,1536] x [1536,1536]^T
    {
        dim3 grid(DMODEL / 128, ROWS / 128);    // 12 x 32
        gemm_pre<<<grid, 512, PG_SMEM>>>(ahi, alo, bhi, blo, out, ROWS, DMODEL, DMODEL);
    }
}

// round 15
// speedup vs baseline: 3.5388x; 1.0817x over previous
#include <cuda_runtime.h>
#include <cuda_bf16.h>
#include <stdint.h>
#include <math.h>

// Problem constants (fixed by the dataset)
#define BATCH 2
#define SEQ 2048
#define DMODEL 1536
#define NHEADS 16
#define NGROUPS 4
#define HDIM 96
#define QKV_OUT 2304            // 16*96 + 2*4*96
#define ROWS (BATCH * SEQ)      // 4096

// Scratch (allocation-free rule: __device__ globals)
__device__ float g_qkv[(size_t)ROWS * QKV_OUT];   // ~37.7 MB
__device__ float g_attn[(size_t)ROWS * DMODEL];   // ~25.2 MB
// bf16 hi/lo planes for GEMM operands (A reused for x and attn; B for weights)
__device__ __nv_bfloat16 c_ahi[(size_t)ROWS * DMODEL];
__device__ __nv_bfloat16 c_alo[(size_t)ROWS * DMODEL];
__device__ __nv_bfloat16 c_bhi[(size_t)QKV_OUT * DMODEL];
__device__ __nv_bfloat16 c_blo[(size_t)QKV_OUT * DMODEL];

// ---------------------------------------------------------------------------
// BF16 3-term split helpers (GEMM path).
// ---------------------------------------------------------------------------
__device__ __forceinline__ uint2 split2(float a, float b) {
    unsigned hi;
    asm("cvt.rn.bf16x2.f32 %0, %1, %2;" : "=r"(hi) : "f"(b), "f"(a));
    float ha = __uint_as_float(hi << 16);
    float hb = __uint_as_float(hi & 0xffff0000u);
    float ra = a - ha;
    float rb = b - hb;
    unsigned lo;
    asm("cvt.rn.bf16x2.f32 %0, %1, %2;" : "=r"(lo) : "f"(rb), "f"(ra));
    return make_uint2(hi, lo);
}

// fp16x2 pack (a in LOW half = earlier element)
__device__ __forceinline__ unsigned pack_f16(float a, float b) {
    unsigned r;
    asm("cvt.rn.f16x2.f32 %0, %1, %2;" : "=r"(r) : "f"(b), "f"(a));
    return r;
}

__device__ __forceinline__ void mma_bf16(float d[4],
                                         unsigned a0, unsigned a1, unsigned a2, unsigned a3,
                                         unsigned b0, unsigned b1) {
    asm volatile(
        "mma.sync.aligned.m16n8k16.row.col.f32.bf16.bf16.f32 "
        "{%0,%1,%2,%3}, {%4,%5,%6,%7}, {%8,%9}, {%0,%1,%2,%3};\n"
        : "+f"(d[0]), "+f"(d[1]), "+f"(d[2]), "+f"(d[3])
        : "r"(a0), "r"(a1), "r"(a2), "r"(a3), "r"(b0), "r"(b1));
}

__device__ __forceinline__ void mma_f16(float d[4],
                                        unsigned a0, unsigned a1, unsigned a2, unsigned a3,
                                        unsigned b0, unsigned b1) {
    asm volatile(
        "mma.sync.aligned.m16n8k16.row.col.f32.f16.f16.f32 "
        "{%0,%1,%2,%3}, {%4,%5,%6,%7}, {%8,%9}, {%0,%1,%2,%3};\n"
        : "+f"(d[0]), "+f"(d[1]), "+f"(d[2]), "+f"(d[3])
        : "r"(a0), "r"(a1), "r"(a2), "r"(a3), "r"(b0), "r"(b1));
}

__device__ __forceinline__ void ldsm4(uint32_t addr, unsigned& r0, unsigned& r1,
                                      unsigned& r2, unsigned& r3) {
    asm volatile("ldmatrix.sync.aligned.m8n8.x4.shared.b16 {%0,%1,%2,%3}, [%4];"
                 : "=r"(r0), "=r"(r1), "=r"(r2), "=r"(r3) : "r"(addr));
}

__device__ __forceinline__ void cpasync16(uint32_t dst, const void* src) {
    asm volatile("cp.async.cg.shared.global [%0], [%1], 16;"
                 :: "r"(dst), "l"(src) : "memory");
}

// ---------------------------------------------------------------------------
// Elementwise split: fp32 -> (hi bf16 plane, lo bf16 plane). 4 floats/thread.
// ---------------------------------------------------------------------------
__global__ void convert_split(const float* __restrict__ src,
                              __nv_bfloat16* __restrict__ hi,
                              __nv_bfloat16* __restrict__ lo, int n4) {
    int idx = blockIdx.x * blockDim.x + threadIdx.x;
    if (idx >= n4) return;
    float4 v = ((const float4*)src)[idx];
    uint2 s0 = split2(v.x, v.y);
    uint2 s1 = split2(v.z, v.w);
    ((uint2*)hi)[idx] = make_uint2(s0.x, s1.x);
    ((uint2*)lo)[idx] = make_uint2(s0.y, s1.y);
}

// ---------------------------------------------------------------------------
// Pre-split bf16x3 GEMM, 2-CTA/SM version.
// Block 128x128, BK=32, 256 threads (8 warps 4m x 2n, warp tile 32x64).
// Smem: 3 stages x 4 planes (Ahi,Alo,Bhi,Blo), each plane 128 rows x 64B with
// XOR swizzle: 16B chunk c of row r stored at chunk (c ^ ((r>>1)&3)).
//   - ldmatrix 8-row phase banks: 16r + 4(c^((r>>1)&3)) mod 32 -> all distinct.
//   - the XOR term is lane-constant: xr = (lane&7)>>1.
// Stage = 32KB, 3 stages = 96KB -> 2 CTAs/SM; regs capped 128 by launch bounds.
// Single __syncthreads per chunk (bottom barrier provably redundant).
// ---------------------------------------------------------------------------
#define SBK 32
#define SPLANE 8192
#define SSTG (4 * SPLANE)                // 32768
#define SNST 3
#define SG_SMEM (SNST * SSTG)            // 98304

__global__ __launch_bounds__(256, 2) void gemm_sw(const __nv_bfloat16* __restrict__ Ahi,
                                                  const __nv_bfloat16* __restrict__ Alo,
                                                  const __nv_bfloat16* __restrict__ Bhi,
                                                  const __nv_bfloat16* __restrict__ Blo,
                                                  float* __restrict__ C,
                                                  int M, int N, int K) {
    extern __shared__ __align__(128) char smem[];
    const uint32_t sbase = (uint32_t)__cvta_generic_to_shared(smem);

    const int tid = threadIdx.x;
    const int lane = tid & 31;
    const int warp = tid >> 5;           // 0..7
    const int gid = lane >> 2;
    const int tig = lane & 3;
    const int wm = (warp >> 1) * 32;     // 0,32,64,96
    const int wn = (warp & 1) * 64;      // 0,64
    const int row0 = blockIdx.y * 128;
    const int col0 = blockIdx.x * 128;

    // ---- loader mapping: plane = tid>>6, t = tid&63 -> rows 2t, 2t+1 ----
    const int lplane = tid >> 6;
    const int lt = tid & 63;
    const uint32_t lxr = (uint32_t)(lt & 3);           // (r>>1)&3, same for 2t,2t+1
    const __nv_bfloat16* gp0;
    {
        const __nv_bfloat16* base;
        int grow = (lplane < 2) ? row0 : col0;
        if (lplane == 0)      base = Ahi;
        else if (lplane == 1) base = Alo;
        else if (lplane == 2) base = Bhi;
        else                  base = Blo;
        gp0 = base + (size_t)(grow + 2 * lt) * K;
    }
    const __nv_bfloat16* gp1 = gp0 + K;
    const uint32_t ld0 = (uint32_t)lplane * SPLANE + (uint32_t)(2 * lt) * 64;
    const uint32_t ld1 = ld0 + 64;

    // ---- fragment lane constants ----
    const uint32_t xr = (uint32_t)((lane & 7) >> 1);
    const int kca = (lane >> 4) & 1;     // A: k-chunk select
    const int kcb = (lane >> 3) & 1;     // B: k-chunk select (swapped roles)
    const uint32_t rba0 = (uint32_t)(wm + ((lane >> 3) & 1) * 8 + (lane & 7)) * 64;
    const uint32_t rba1 = rba0 + 16 * 64;
    uint32_t rbb[4];
#pragma unroll
    for (int nb = 0; nb < 4; nb++)
        rbb[nb] = (uint32_t)(wn + nb * 16 + ((lane >> 4) & 1) * 8 + (lane & 7)) * 64;

    float acc[2][8][4];
#pragma unroll
    for (int mi = 0; mi < 2; mi++)
#pragma unroll
        for (int ni = 0; ni < 8; ni++)
#pragma unroll
            for (int r = 0; r < 4; r++) acc[mi][ni][r] = 0.f;

    const int nch = K / SBK;             // 48

    // ---- prologue: chunks 0,1 -> stages 0,1 ----
#pragma unroll
    for (int p = 0; p < 2; p++) {
        uint32_t d = sbase + (uint32_t)p * SSTG;
        const __nv_bfloat16* s0 = gp0 + p * SBK;
        const __nv_bfloat16* s1 = gp1 + p * SBK;
#pragma unroll
        for (int c = 0; c < 4; c++) {
            uint32_t co = ((uint32_t)c ^ lxr) << 4;
            cpasync16(d + ld0 + co, s0 + c * 8);
            cpasync16(d + ld1 + co, s1 + c * 8);
        }
        asm volatile("cp.async.commit_group;" ::: "memory");
    }

    int stage = 0;
    for (int c = 0; c < nch; c++) {
        if (c < nch - 1)
            asm volatile("cp.async.wait_group 1;" ::: "memory");
        else
            asm volatile("cp.async.wait_group 0;" ::: "memory");
        __syncthreads();

        // issue chunk c+2 into stage (c+2)%3
        if (c + 2 < nch) {
            int s2 = stage + 2; if (s2 >= SNST) s2 -= SNST;
            uint32_t d = sbase + (uint32_t)s2 * SSTG;
            const __nv_bfloat16* s0 = gp0 + (c + 2) * SBK;
            const __nv_bfloat16* s1 = gp1 + (c + 2) * SBK;
#pragma unroll
            for (int cc = 0; cc < 4; cc++) {
                uint32_t co = ((uint32_t)cc ^ lxr) << 4;
                cpasync16(d + ld0 + co, s0 + cc * 8);
                cpasync16(d + ld1 + co, s1 + cc * 8);
            }
            asm volatile("cp.async.commit_group;" ::: "memory");
        }

        const uint32_t sa = sbase + (uint32_t)stage * SSTG;
#pragma unroll
        for (int ks = 0; ks < 2; ks++) {
            const uint32_t ca = ((uint32_t)(ks * 2 + kca) ^ xr) << 4;
            const uint32_t cb = ((uint32_t)(ks * 2 + kcb) ^ xr) << 4;

            unsigned ah[2][4], al[2][4];
            ldsm4(sa + rba0 + ca, ah[0][0], ah[0][1], ah[0][2], ah[0][3]);
            ldsm4(sa + rba1 + ca, ah[1][0], ah[1][1], ah[1][2], ah[1][3]);
            ldsm4(sa + SPLANE + rba0 + ca, al[0][0], al[0][1], al[0][2], al[0][3]);
            ldsm4(sa + SPLANE + rba1 + ca, al[1][0], al[1][1], al[1][2], al[1][3]);

#pragma unroll
            for (int nb = 0; nb < 4; nb++) {
                unsigned bh[4], bl[4];
                ldsm4(sa + 2 * SPLANE + rbb[nb] + cb, bh[0], bh[1], bh[2], bh[3]);
                ldsm4(sa + 3 * SPLANE + rbb[nb] + cb, bl[0], bl[1], bl[2], bl[3]);
                // x4 matrices: {n8_0 k0, n8_0 k1, n8_1 k0, n8_1 k1}
#pragma unroll
                for (int half = 0; half < 2; half++) {
                    const int ni = nb * 2 + half;
                    unsigned b0h = bh[half * 2], b1h = bh[half * 2 + 1];
                    unsigned b0l = bl[half * 2], b1l = bl[half * 2 + 1];
#pragma unroll
                    for (int mi = 0; mi < 2; mi++) {
                        mma_bf16(acc[mi][ni], ah[mi][0], ah[mi][1], ah[mi][2], ah[mi][3], b0h, b1h);
                        mma_bf16(acc[mi][ni], ah[mi][0], ah[mi][1], ah[mi][2], ah[mi][3], b0l, b1l);
                        mma_bf16(acc[mi][ni], al[mi][0], al[mi][1], al[mi][2], al[mi][3], b0h, b1h);
                    }
                }
            }
        }
        if (++stage >= SNST) stage -= SNST;
    }

    // ---- epilogue ----
#pragma unroll
    for (int mi = 0; mi < 2; mi++)
#pragma unroll
        for (int ni = 0; ni < 8; ni++) {
            int r = row0 + wm + mi * 16 + gid;
            int cc = col0 + wn + ni * 8 + (tig << 1);
            *(float2*)&C[(size_t)r * N + cc]       = make_float2(acc[mi][ni][0], acc[mi][ni][1]);
            *(float2*)&C[(size_t)(r + 8) * N + cc] = make_float2(acc[mi][ni][2], acc[mi][ni][3]);
        }
}

// ---------------------------------------------------------------------------
// RoPE-3D (powf -> ex2.approx, sincosf -> __sincosf; angle <= 15 so fast-trig
// abs error ~1e-5, well within budget)
// ---------------------------------------------------------------------------
__global__ void rope_kernel(float* __restrict__ qkv,
                            const int* __restrict__ p_gh,
                            const int* __restrict__ p_gw) {
    int idx = blockIdx.x * blockDim.x + threadIdx.x;
    const int TOTAL = ROWS * 20 * 48;
    if (idx >= TOTAL) return;

    int pair = idx % 48;
    int head = (idx / 48) % 20;
    int row = idx / (48 * 20);
    int n = row % SEQ;

    int H = p_gh ? *p_gh : 16;
    int W = p_gw ? *p_gw : 16;
    int w = n % W;
    int h = (n / W) % H;
    int t = n / (W * H);

    int axis = pair / 16;
    int i = pair % 16;
    float pos = (float)(axis == 0 ? t : (axis == 1 ? h : w));

    // freq = 10000^(-i/16) = 2^(-i * log2(10000)/16)
    float e = (float)i * (-13.2877123795494f / 16.0f);
    float freq;
    asm("ex2.approx.f32 %0, %1;" : "=f"(freq) : "f"(e));
    float ang = pos * freq;
    float s, c;
    __sincosf(ang, &s, &c);

    int coloff = (head < 16) ? head * HDIM : (1536 + (head - 16) * HDIM);
    size_t base = (size_t)row * QKV_OUT + coloff + axis * 32 + 2 * i;
    float x0 = qkv[base];
    float x1 = qkv[base + 1];
    qkv[base] = x0 * c - x1 * s;
    qkv[base + 1] = x0 * s + x1 * c;
}

// ---------------------------------------------------------------------------
// FP16 single-term tensor-core flash attention (unchanged from R14 — passing).
// ---------------------------------------------------------------------------
#define AQT 128
#define AKT 64
#define QRS 136
#define KRS 72
#define VRS 104
#define ATT_SMEM ((48 * QRS + 48 * KRS + 32 * VRS) * (int)sizeof(unsigned))  // 53248 B

__global__ __launch_bounds__(256) void attn_f16(const float* __restrict__ qkv,
                                                float* __restrict__ out) {
    extern __shared__ unsigned smu[];
    unsigned* Qs = smu;                 // [48][QRS]
    unsigned* Ks = Qs + 48 * QRS;       // [48][KRS]
    unsigned* Vs = Ks + 48 * KRS;       // [32][VRS]

    const int b = blockIdx.z;
    const int hh = blockIdx.y;
    const int g = hh >> 2;
    const int q0 = blockIdx.x * AQT;

    const int tid = threadIdx.x;
    const int lane = tid & 31;
    const int warp = tid >> 5;
    const int gid = lane >> 2;
    const int tig = lane & 3;
    const int wq = warp * 16;

    const float scale = rsqrtf((float)HDIM);

    {
        const int row = tid & 127;
        const int half = tid >> 7;
        const float* src = qkv + ((size_t)(b * SEQ + q0 + row)) * QKV_OUT + hh * HDIM + half * 48;
#pragma unroll
        for (int i = 0; i < 12; i++) {
            float4 v = *(const float4*)(src + i * 4);
            int j = half * 24 + i * 2;
            Qs[j * QRS + row]       = pack_f16(v.x * scale, v.y * scale);
            Qs[(j + 1) * QRS + row] = pack_f16(v.z * scale, v.w * scale);
        }
    }

    float o[12][4];
#pragma unroll
    for (int ni = 0; ni < 12; ni++)
#pragma unroll
        for (int r = 0; r < 4; r++) o[ni][r] = 0.f;
    float m0 = -3.0e38f, m1 = -3.0e38f;
    float l0 = 0.f, l1 = 0.f;

    for (int kt = 0; kt < SEQ / AKT; kt++) {
        __syncthreads();
        {
            const int key = tid & 63;
            const int third = tid >> 6;
            const float* src = qkv + ((size_t)(b * SEQ + kt * AKT + key)) * QKV_OUT
                               + 1536 + g * HDIM + third * 24;
#pragma unroll
            for (int i = 0; i < 6; i++) {
                float4 v = *(const float4*)(src + i * 4);
                int j = third * 12 + i * 2;
                Ks[j * KRS + key]       = pack_f16(v.x, v.y);
                Ks[(j + 1) * KRS + key] = pack_f16(v.z, v.w);
            }
        }
        {
            const int kp = tid & 31;
            const int oct = tid >> 5;
            const float* srcA = qkv + ((size_t)(b * SEQ + kt * AKT + 2 * kp)) * QKV_OUT
                                + 1536 + NGROUPS * HDIM + g * HDIM + oct * 12;
            const float* srcB = srcA + QKV_OUT;
#pragma unroll
            for (int i = 0; i < 3; i++) {
                float4 va = *(const float4*)(srcA + i * 4);
                float4 vb = *(const float4*)(srcB + i * 4);
                unsigned* dst = &Vs[kp * VRS + oct * 12 + i * 4];
                *(uint4*)dst = make_uint4(pack_f16(va.x, vb.x), pack_f16(va.y, vb.y),
                                          pack_f16(va.z, vb.z), pack_f16(va.w, vb.w));
            }
        }
        __syncthreads();

        float sacc[8][4];
#pragma unroll
        for (int ni = 0; ni < 8; ni++)
#pragma unroll
            for (int r = 0; r < 4; r++) sacc[ni][r] = 0.f;

#pragma unroll
        for (int ks = 0; ks < HDIM / 16; ks++) {
            const int j0 = ks * 8 + tig;
            const int j1 = j0 + 4;
            unsigned a0 = Qs[j0 * QRS + wq + gid];
            unsigned a1 = Qs[j0 * QRS + wq + gid + 8];
            unsigned a2 = Qs[j1 * QRS + wq + gid];
            unsigned a3 = Qs[j1 * QRS + wq + gid + 8];
#pragma unroll
            for (int ni = 0; ni < 8; ni++) {
                unsigned b0 = Ks[j0 * KRS + ni * 8 + gid];
                unsigned b1 = Ks[j1 * KRS + ni * 8 + gid];
                mma_f16(sacc[ni], a0, a1, a2, a3, b0, b1);
            }
        }

        float tmax0 = -3.0e38f, tmax1 = -3.0e38f;
#pragma unroll
        for (int ni = 0; ni < 8; ni++) {
            tmax0 = fmaxf(tmax0, fmaxf(sacc[ni][0], sacc[ni][1]));
            tmax1 = fmaxf(tmax1, fmaxf(sacc[ni][2], sacc[ni][3]));
        }
        tmax0 = fmaxf(tmax0, __shfl_xor_sync(0xffffffffu, tmax0, 1));
        tmax0 = fmaxf(tmax0, __shfl_xor_sync(0xffffffffu, tmax0, 2));
        tmax1 = fmaxf(tmax1, __shfl_xor_sync(0xffffffffu, tmax1, 1));
        tmax1 = fmaxf(tmax1, __shfl_xor_sync(0xffffffffu, tmax1, 2));

        float mn0 = fmaxf(m0, tmax0);
        float mn1 = fmaxf(m1, tmax1);
        float corr0 = __expf(m0 - mn0);
        float corr1 = __expf(m1 - mn1);
        m0 = mn0; m1 = mn1;

        float sum0 = 0.f, sum1 = 0.f;
#pragma unroll
        for (int ni = 0; ni < 8; ni++) {
            float p0 = __expf(sacc[ni][0] - m0);
            float p1 = __expf(sacc[ni][1] - m0);
            float p2 = __expf(sacc[ni][2] - m1);
            float p3 = __expf(sacc[ni][3] - m1);
            sacc[ni][0] = p0; sacc[ni][1] = p1; sacc[ni][2] = p2; sacc[ni][3] = p3;
            sum0 += p0 + p1; sum1 += p2 + p3;
        }
        l0 = l0 * corr0 + sum0;
        l1 = l1 * corr1 + sum1;

#pragma unroll
        for (int ni = 0; ni < 12; ni++) {
            o[ni][0] *= corr0; o[ni][1] *= corr0;
            o[ni][2] *= corr1; o[ni][3] *= corr1;
        }

#pragma unroll
        for (int ks = 0; ks < AKT / 16; ks++) {
            unsigned p0 = pack_f16(sacc[2 * ks][0],     sacc[2 * ks][1]);
            unsigned p1 = pack_f16(sacc[2 * ks][2],     sacc[2 * ks][3]);
            unsigned p2 = pack_f16(sacc[2 * ks + 1][0], sacc[2 * ks + 1][1]);
            unsigned p3 = pack_f16(sacc[2 * ks + 1][2], sacc[2 * ks + 1][3]);
            const int j0 = ks * 8 + tig;
            const int j1 = j0 + 4;
#pragma unroll
            for (int ni = 0; ni < 12; ni++) {
                unsigned b0 = Vs[j0 * VRS + ni * 8 + gid];
                unsigned b1 = Vs[j1 * VRS + ni * 8 + gid];
                mma_f16(o[ni], p0, p1, p2, p3, b0, b1);
            }
        }
    }

    l0 += __shfl_xor_sync(0xffffffffu, l0, 1);
    l0 += __shfl_xor_sync(0xffffffffu, l0, 2);
    l1 += __shfl_xor_sync(0xffffffffu, l1, 1);
    l1 += __shfl_xor_sync(0xffffffffu, l1, 2);
    float inv0 = 1.f / l0;
    float inv1 = 1.f / l1;

    const int r0 = b * SEQ + q0 + wq + gid;
#pragma unroll
    for (int ni = 0; ni < 12; ni++) {
        int c = hh * HDIM + ni * 8 + (tig << 1);
        *(float2*)&out[(size_t)r0 * DMODEL + c] =
            make_float2(o[ni][0] * inv0, o[ni][1] * inv0);
        *(float2*)&out[(size_t)(r0 + 8) * DMODEL + c] =
            make_float2(o[ni][2] * inv1, o[ni][3] * inv1);
    }
}

// ---------------------------------------------------------------------------
extern "C" void kernel_launch(void* const* d_in, const int* in_sizes, int n_in,
                              void* d_out, int out_size) {
    const float* x = (const float*)d_in[0];
    const float* w_qkv = (const float*)d_in[1];
    const float* w_o = (const float*)d_in[2];
    const int* gh = (n_in >= 6) ? (const int*)d_in[4] : nullptr;
    const int* gw = (n_in >= 6) ? (const int*)d_in[5] : nullptr;
    float* out = (float*)d_out;

    float* qkv = nullptr;
    float* attn = nullptr;
    __nv_bfloat16 *ahi, *alo, *bhi, *blo;
    cudaGetSymbolAddress((void**)&qkv, g_qkv);
    cudaGetSymbolAddress((void**)&attn, g_attn);
    cudaGetSymbolAddress((void**)&ahi, c_ahi);
    cudaGetSymbolAddress((void**)&alo, c_alo);
    cudaGetSymbolAddress((void**)&bhi, c_bhi);
    cudaGetSymbolAddress((void**)&blo, c_blo);

    static int smem_set = 0;
    if (!smem_set) {
        cudaFuncSetAttribute(attn_f16, cudaFuncAttributeMaxDynamicSharedMemorySize, ATT_SMEM);
        cudaFuncSetAttribute(gemm_sw, cudaFuncAttributeMaxDynamicSharedMemorySize, SG_SMEM);
        smem_set = 1;
    }

    // 1) split x and w_qkv into bf16 hi/lo planes
    {
        int n4 = ROWS * DMODEL / 4;
        convert_split<<<(n4 + 255) / 256, 256>>>(x, ahi, alo, n4);
        int m4 = QKV_OUT * DMODEL / 4;
        convert_split<<<(m4 + 255) / 256, 256>>>(w_qkv, bhi, blo, m4);
    }

    // 2) QKV projection: [4096,1536] x [2304,1536]^T
    {
        dim3 grid(QKV_OUT / 128, ROWS / 128);   // 18 x 32
        gemm_sw<<<grid, 256, SG_SMEM>>>(ahi, alo, bhi, blo, qkv, ROWS, QKV_OUT, DMODEL);
    }

    // 3) RoPE
    {
        int total = ROWS * 20 * 48;
        rope_kernel<<<(total + 255) / 256, 256>>>(qkv, gh, gw);
    }

    // 4) FP16 tensor-core flash attention
    {
        dim3 grid(SEQ / AQT, NHEADS, BATCH);    // 16 x 16 x 2
        attn_f16<<<grid, 256, ATT_SMEM>>>(qkv, attn);
    }

    // 5) split attn output and w_o
    {
        int n4 = ROWS * DMODEL / 4;
        convert_split<<<(n4 + 255) / 256, 256>>>(attn, ahi, alo, n4);
        int m4 = DMODEL * DMODEL / 4;
        convert_split<<<(m4 + 255) / 256, 256>>>(w_o, bhi, blo, m4);
    }

    // 6) Output projection: [4096,1536] x [1536,1536]^T
    {
        dim3 grid(DMODEL / 128, ROWS / 128);    // 12 x 32
        gemm_sw<<<grid, 256, SG_SMEM>>>(ahi, alo, bhi, blo, out, ROWS, DMODEL, DMODEL);
    }
}

// round 17
// speedup vs baseline: 5.2044x; 1.4707x over previous
#include <cuda_runtime.h>
#include <cuda_fp16.h>
#include <cuda_bf16.h>
#include <stdint.h>
#include <math.h>

// Problem constants (fixed by the dataset)
#define BATCH 2
#define SEQ 2048
#define DMODEL 1536
#define NHEADS 16
#define NGROUPS 4
#define HDIM 96
#define QKV_OUT 2304            // 16*96 + 2*4*96
#define ROWS (BATCH * SEQ)      // 4096

// Scratch (allocation-free rule: __device__ globals)
__device__ float g_qkv[(size_t)ROWS * QKV_OUT];   // ~37.7 MB
// fp16 operand buffers
__device__ __half c_xf16[(size_t)ROWS * DMODEL];      // x (A of QKV proj)
__device__ __half c_af16[(size_t)ROWS * DMODEL];      // attn out (A of O proj)
__device__ __half c_wf16[(size_t)QKV_OUT * DMODEL];   // weights (B), reused

// fp16x2 pack (a in LOW half = earlier element)
__device__ __forceinline__ unsigned pack_f16(float a, float b) {
    unsigned r;
    asm("cvt.rn.f16x2.f32 %0, %1, %2;" : "=r"(r) : "f"(b), "f"(a));
    return r;
}

__device__ __forceinline__ void mma_f16(float d[4],
                                        unsigned a0, unsigned a1, unsigned a2, unsigned a3,
                                        unsigned b0, unsigned b1) {
    asm volatile(
        "mma.sync.aligned.m16n8k16.row.col.f32.f16.f16.f32 "
        "{%0,%1,%2,%3}, {%4,%5,%6,%7}, {%8,%9}, {%0,%1,%2,%3};\n"
        : "+f"(d[0]), "+f"(d[1]), "+f"(d[2]), "+f"(d[3])
        : "r"(a0), "r"(a1), "r"(a2), "r"(a3), "r"(b0), "r"(b1));
}

__device__ __forceinline__ void ldsm4(uint32_t addr, unsigned& r0, unsigned& r1,
                                      unsigned& r2, unsigned& r3) {
    asm volatile("ldmatrix.sync.aligned.m8n8.x4.shared.b16 {%0,%1,%2,%3}, [%4];"
                 : "=r"(r0), "=r"(r1), "=r"(r2), "=r"(r3) : "r"(addr));
}

__device__ __forceinline__ void cpasync16(uint32_t dst, const void* src) {
    asm volatile("cp.async.cg.shared.global [%0], [%1], 16;"
                 :: "r"(dst), "l"(src) : "memory");
}

// ---------------------------------------------------------------------------
// Elementwise fp32 -> fp16 convert. 4 floats/thread.
// ---------------------------------------------------------------------------
__global__ void convert_f16(const float* __restrict__ src,
                            __half* __restrict__ dst, int n4) {
    int idx = blockIdx.x * blockDim.x + threadIdx.x;
    if (idx >= n4) return;
    float4 v = ((const float4*)src)[idx];
    ((uint2*)dst)[idx] = make_uint2(pack_f16(v.x, v.y), pack_f16(v.z, v.w));
}

// ---------------------------------------------------------------------------
// FP16 single-term GEMM: C[M,N] = A[M,K] * B[N,K]^T  (fp16 in, fp32 out).
// Block 128x128, BK=64, 256 threads (8 warps 4m x 2n, warp tile 32x64).
// Smem: 3 stages x 2 planes (A, B); plane = 128 rows x 128B, XOR swizzle:
// 16B chunk c of row r stored at chunk (c ^ (r&7)) -> ldmatrix 8-row phase
// and cp.async stores both conflict-free. Stage 32KB, 3 stages = 96KB
// -> 2 CTAs/SM; one __syncthreads per 64-wide K chunk (24 total).
// ---------------------------------------------------------------------------
#define FBK 64
#define FPLANE 16384                     // 128 rows x 128 B
#define FSTG (2 * FPLANE)                // 32768
#define FNST 3
#define FG_SMEM (FNST * FSTG)            // 98304

__global__ __launch_bounds__(256, 2) void gemm_f16(const __half* __restrict__ A,
                                                   const __half* __restrict__ B,
                                                   float* __restrict__ C,
                                                   int M, int N, int K) {
    extern __shared__ __align__(128) char smem[];
    const uint32_t sbase = (uint32_t)__cvta_generic_to_shared(smem);

    const int tid = threadIdx.x;
    const int lane = tid & 31;
    const int warp = tid >> 5;           // 0..7
    const int gid = lane >> 2;
    const int tig = lane & 3;
    const int wm = (warp >> 1) * 32;     // 0,32,64,96
    const int wn = (warp & 1) * 64;      // 0,64
    const int row0 = blockIdx.y * 128;
    const int col0 = blockIdx.x * 128;

    // ---- loader mapping: plane = tid>>7 (0=A,1=B), row = tid&127 ----
    const int lplane = tid >> 7;
    const int lrow = tid & 127;
    const __half* gsrc = lplane ? (B + (size_t)(col0 + lrow) * K)
                                : (A + (size_t)(row0 + lrow) * K);
    const uint32_t ldst = (uint32_t)lplane * FPLANE + (uint32_t)lrow * 128;
    const uint32_t lxr = (uint32_t)(lrow & 7);

    // ---- fragment lane constants (row&7 == lane&7 for all fragment rows) ----
    const uint32_t xr = (uint32_t)(lane & 7);
    const int kca = (lane >> 4) & 1;     // A: k8-chunk select within k16
    const int kcb = (lane >> 3) & 1;     // B: k8-chunk select
    const uint32_t rba0 = (uint32_t)(wm + ((lane >> 3) & 1) * 8 + (lane & 7)) * 128;
    const uint32_t rba1 = rba0 + 16 * 128;
    uint32_t rbb[4];
#pragma unroll
    for (int nb = 0; nb < 4; nb++)
        rbb[nb] = (uint32_t)(wn + nb * 16 + ((lane >> 4) & 1) * 8 + (lane & 7)) * 128;

    float acc[2][8][4];
#pragma unroll
    for (int mi = 0; mi < 2; mi++)
#pragma unroll
        for (int ni = 0; ni < 8; ni++)
#pragma unroll
            for (int r = 0; r < 4; r++) acc[mi][ni][r] = 0.f;

    const int nch = K / FBK;             // 24

    // ---- prologue: chunks 0,1 -> stages 0,1 ----
#pragma unroll
    for (int p = 0; p < 2; p++) {
        uint32_t d = sbase + (uint32_t)p * FSTG + ldst;
        const __half* s = gsrc + p * FBK;
#pragma unroll
        for (int c = 0; c < 8; c++)
            cpasync16(d + (((uint32_t)c ^ lxr) << 4), s + c * 8);
        asm volatile("cp.async.commit_group;" ::: "memory");
    }

    int stage = 0;
    for (int c = 0; c < nch; c++) {
        if (c < nch - 1)
            asm volatile("cp.async.wait_group 1;" ::: "memory");
        else
            asm volatile("cp.async.wait_group 0;" ::: "memory");
        __syncthreads();

        // issue chunk c+2 into stage (c+2)%3
        if (c + 2 < nch) {
            int s2 = stage + 2; if (s2 >= FNST) s2 -= FNST;
            uint32_t d = sbase + (uint32_t)s2 * FSTG + ldst;
            const __half* s = gsrc + (c + 2) * FBK;
#pragma unroll
            for (int cc = 0; cc < 8; cc++)
                cpasync16(d + (((uint32_t)cc ^ lxr) << 4), s + cc * 8);
            asm volatile("cp.async.commit_group;" ::: "memory");
        }

        const uint32_t sa = sbase + (uint32_t)stage * FSTG;
#pragma unroll
        for (int ks = 0; ks < 4; ks++) {
            const uint32_t ca = ((uint32_t)(ks * 2 + kca) ^ xr) << 4;
            const uint32_t cb = ((uint32_t)(ks * 2 + kcb) ^ xr) << 4;

            unsigned a[2][4];
            ldsm4(sa + rba0 + ca, a[0][0], a[0][1], a[0][2], a[0][3]);
            ldsm4(sa + rba1 + ca, a[1][0], a[1][1], a[1][2], a[1][3]);

#pragma unroll
            for (int nb = 0; nb < 4; nb++) {
                unsigned bf[4];
                ldsm4(sa + FPLANE + rbb[nb] + cb, bf[0], bf[1], bf[2], bf[3]);
#pragma unroll
                for (int half = 0; half < 2; half++) {
                    const int ni = nb * 2 + half;
                    unsigned b0 = bf[half * 2], b1 = bf[half * 2 + 1];
#pragma unroll
                    for (int mi = 0; mi < 2; mi++)
                        mma_f16(acc[mi][ni], a[mi][0], a[mi][1], a[mi][2], a[mi][3], b0, b1);
                }
            }
        }
        if (++stage >= FNST) stage -= FNST;
    }

    // ---- epilogue ----
#pragma unroll
    for (int mi = 0; mi < 2; mi++)
#pragma unroll
        for (int ni = 0; ni < 8; ni++) {
            int r = row0 + wm + mi * 16 + gid;
            int cc = col0 + wn + ni * 8 + (tig << 1);
            *(float2*)&C[(size_t)r * N + cc]       = make_float2(acc[mi][ni][0], acc[mi][ni][1]);
            *(float2*)&C[(size_t)(r + 8) * N + cc] = make_float2(acc[mi][ni][2], acc[mi][ni][3]);
        }
}

// ---------------------------------------------------------------------------
// RoPE-3D (fast-math variant, unchanged from R15)
// ---------------------------------------------------------------------------
__global__ void rope_kernel(float* __restrict__ qkv,
                            const int* __restrict__ p_gh,
                            const int* __restrict__ p_gw) {
    int idx = blockIdx.x * blockDim.x + threadIdx.x;
    const int TOTAL = ROWS * 20 * 48;
    if (idx >= TOTAL) return;

    int pair = idx % 48;
    int head = (idx / 48) % 20;
    int row = idx / (48 * 20);
    int n = row % SEQ;

    int H = p_gh ? *p_gh : 16;
    int W = p_gw ? *p_gw : 16;
    int w = n % W;
    int h = (n / W) % H;
    int t = n / (W * H);

    int axis = pair / 16;
    int i = pair % 16;
    float pos = (float)(axis == 0 ? t : (axis == 1 ? h : w));

    float e = (float)i * (-13.2877123795494f / 16.0f);
    float freq;
    asm("ex2.approx.f32 %0, %1;" : "=f"(freq) : "f"(e));
    float ang = pos * freq;
    float s, c;
    __sincosf(ang, &s, &c);

    int coloff = (head < 16) ? head * HDIM : (1536 + (head - 16) * HDIM);
    size_t base = (size_t)row * QKV_OUT + coloff + axis * 32 + 2 * i;
    float x0 = qkv[base];
    float x1 = qkv[base + 1];
    qkv[base] = x0 * c - x1 * s;
    qkv[base + 1] = x0 * s + x1 * c;
}

// ---------------------------------------------------------------------------
// FP16 single-term tensor-core flash attention (R14 structure; epilogue now
// writes fp16 directly into the O-proj A-operand buffer).
// ---------------------------------------------------------------------------
#define AQT 128
#define AKT 64
#define QRS 136
#define KRS 72
#define VRS 104
#define ATT_SMEM ((48 * QRS + 48 * KRS + 32 * VRS) * (int)sizeof(unsigned))  // 53248 B

__global__ __launch_bounds__(256) void attn_f16(const float* __restrict__ qkv,
                                                unsigned* __restrict__ out16) {
    extern __shared__ unsigned smu[];
    unsigned* Qs = smu;                 // [48][QRS]
    unsigned* Ks = Qs + 48 * QRS;       // [48][KRS]
    unsigned* Vs = Ks + 48 * KRS;       // [32][VRS]

    const int b = blockIdx.z;
    const int hh = blockIdx.y;
    const int g = hh >> 2;
    const int q0 = blockIdx.x * AQT;

    const int tid = threadIdx.x;
    const int lane = tid & 31;
    const int warp = tid >> 5;
    const int gid = lane >> 2;
    const int tig = lane & 3;
    const int wq = warp * 16;

    const float scale = rsqrtf((float)HDIM);

    {
        const int row = tid & 127;
        const int half = tid >> 7;
        const float* src = qkv + ((size_t)(b * SEQ + q0 + row)) * QKV_OUT + hh * HDIM + half * 48;
#pragma unroll
        for (int i = 0; i < 12; i++) {
            float4 v = *(const float4*)(src + i * 4);
            int j = half * 24 + i * 2;
            Qs[j * QRS + row]       = pack_f16(v.x * scale, v.y * scale);
            Qs[(j + 1) * QRS + row] = pack_f16(v.z * scale, v.w * scale);
        }
    }

    float o[12][4];
#pragma unroll
    for (int ni = 0; ni < 12; ni++)
#pragma unroll
        for (int r = 0; r < 4; r++) o[ni][r] = 0.f;
    float m0 = -3.0e38f, m1 = -3.0e38f;
    float l0 = 0.f, l1 = 0.f;

    for (int kt = 0; kt < SEQ / AKT; kt++) {
        __syncthreads();
        {
            const int key = tid & 63;
            const int third = tid >> 6;
            const float* src = qkv + ((size_t)(b * SEQ + kt * AKT + key)) * QKV_OUT
                               + 1536 + g * HDIM + third * 24;
#pragma unroll
            for (int i = 0; i < 6; i++) {
                float4 v = *(const float4*)(src + i * 4);
                int j = third * 12 + i * 2;
                Ks[j * KRS + key]       = pack_f16(v.x, v.y);
                Ks[(j + 1) * KRS + key] = pack_f16(v.z, v.w);
            }
        }
        {
            const int kp = tid & 31;
            const int oct = tid >> 5;
            const float* srcA = qkv + ((size_t)(b * SEQ + kt * AKT + 2 * kp)) * QKV_OUT
                                + 1536 + NGROUPS * HDIM + g * HDIM + oct * 12;
            const float* srcB = srcA + QKV_OUT;
#pragma unroll
            for (int i = 0; i < 3; i++) {
                float4 va = *(const float4*)(srcA + i * 4);
                float4 vb = *(const float4*)(srcB + i * 4);
                unsigned* dst = &Vs[kp * VRS + oct * 12 + i * 4];
                *(uint4*)dst = make_uint4(pack_f16(va.x, vb.x), pack_f16(va.y, vb.y),
                                          pack_f16(va.z, vb.z), pack_f16(va.w, vb.w));
            }
        }
        __syncthreads();

        float sacc[8][4];
#pragma unroll
        for (int ni = 0; ni < 8; ni++)
#pragma unroll
            for (int r = 0; r < 4; r++) sacc[ni][r] = 0.f;

#pragma unroll
        for (int ks = 0; ks < HDIM / 16; ks++) {
            const int j0 = ks * 8 + tig;
            const int j1 = j0 + 4;
            unsigned a0 = Qs[j0 * QRS + wq + gid];
            unsigned a1 = Qs[j0 * QRS + wq + gid + 8];
            unsigned a2 = Qs[j1 * QRS + wq + gid];
            unsigned a3 = Qs[j1 * QRS + wq + gid + 8];
#pragma unroll
            for (int ni = 0; ni < 8; ni++) {
                unsigned b0 = Ks[j0 * KRS + ni * 8 + gid];
                unsigned b1 = Ks[j1 * KRS + ni * 8 + gid];
                mma_f16(sacc[ni], a0, a1, a2, a3, b0, b1);
            }
        }

        float tmax0 = -3.0e38f, tmax1 = -3.0e38f;
#pragma unroll
        for (int ni = 0; ni < 8; ni++) {
            tmax0 = fmaxf(tmax0, fmaxf(sacc[ni][0], sacc[ni][1]));
            tmax1 = fmaxf(tmax1, fmaxf(sacc[ni][2], sacc[ni][3]));
        }
        tmax0 = fmaxf(tmax0, __shfl_xor_sync(0xffffffffu, tmax0, 1));
        tmax0 = fmaxf(tmax0, __shfl_xor_sync(0xffffffffu, tmax0, 2));
        tmax1 = fmaxf(tmax1, __shfl_xor_sync(0xffffffffu, tmax1, 1));
        tmax1 = fmaxf(tmax1, __shfl_xor_sync(0xffffffffu, tmax1, 2));

        float mn0 = fmaxf(m0, tmax0);
        float mn1 = fmaxf(m1, tmax1);
        float corr0 = __expf(m0 - mn0);
        float corr1 = __expf(m1 - mn1);
        m0 = mn0; m1 = mn1;

        float sum0 = 0.f, sum1 = 0.f;
#pragma unroll
        for (int ni = 0; ni < 8; ni++) {
            float p0 = __expf(sacc[ni][0] - m0);
            float p1 = __expf(sacc[ni][1] - m0);
            float p2 = __expf(sacc[ni][2] - m1);
            float p3 = __expf(sacc[ni][3] - m1);
            sacc[ni][0] = p0; sacc[ni][1] = p1; sacc[ni][2] = p2; sacc[ni][3] = p3;
            sum0 += p0 + p1; sum1 += p2 + p3;
        }
        l0 = l0 * corr0 + sum0;
        l1 = l1 * corr1 + sum1;

#pragma unroll
        for (int ni = 0; ni < 12; ni++) {
            o[ni][0] *= corr0; o[ni][1] *= corr0;
            o[ni][2] *= corr1; o[ni][3] *= corr1;
        }

#pragma unroll
        for (int ks = 0; ks < AKT / 16; ks++) {
            unsigned p0 = pack_f16(sacc[2 * ks][0],     sacc[2 * ks][1]);
            unsigned p1 = pack_f16(sacc[2 * ks][2],     sacc[2 * ks][3]);
            unsigned p2 = pack_f16(sacc[2 * ks + 1][0], sacc[2 * ks + 1][1]);
            unsigned p3 = pack_f16(sacc[2 * ks + 1][2], sacc[2 * ks + 1][3]);
            const int j0 = ks * 8 + tig;
            const int j1 = j0 + 4;
#pragma unroll
            for (int ni = 0; ni < 12; ni++) {
                unsigned b0 = Vs[j0 * VRS + ni * 8 + gid];
                unsigned b1 = Vs[j1 * VRS + ni * 8 + gid];
                mma_f16(o[ni], p0, p1, p2, p3, b0, b1);
            }
        }
    }

    l0 += __shfl_xor_sync(0xffffffffu, l0, 1);
    l0 += __shfl_xor_sync(0xffffffffu, l0, 2);
    l1 += __shfl_xor_sync(0xffffffffu, l1, 1);
    l1 += __shfl_xor_sync(0xffffffffu, l1, 2);
    float inv0 = 1.f / l0;
    float inv1 = 1.f / l1;

    // fp16x2 epilogue straight into the O-proj A operand
    const int r0 = b * SEQ + q0 + wq + gid;
    const int cp = hh * 48 + tig;        // column-pair base
#pragma unroll
    for (int ni = 0; ni < 12; ni++) {
        out16[(size_t)r0 * (DMODEL / 2) + cp + ni * 4] =
            pack_f16(o[ni][0] * inv0, o[ni][1] * inv0);
        out16[(size_t)(r0 + 8) * (DMODEL / 2) + cp + ni * 4] =
            pack_f16(o[ni][2] * inv1, o[ni][3] * inv1);
    }
}

// ---------------------------------------------------------------------------
extern "C" void kernel_launch(void* const* d_in, const int* in_sizes, int n_in,
                              void* d_out, int out_size) {
    const float* x = (const float*)d_in[0];
    const float* w_qkv = (const float*)d_in[1];
    const float* w_o = (const float*)d_in[2];
    const int* gh = (n_in >= 6) ? (const int*)d_in[4] : nullptr;
    const int* gw = (n_in >= 6) ? (const int*)d_in[5] : nullptr;
    float* out = (float*)d_out;

    float* qkv = nullptr;
    __half *xf, *af, *wf;
    cudaGetSymbolAddress((void**)&qkv, g_qkv);
    cudaGetSymbolAddress((void**)&xf, c_xf16);
    cudaGetSymbolAddress((void**)&af, c_af16);
    cudaGetSymbolAddress((void**)&wf, c_wf16);

    static int smem_set = 0;
    if (!smem_set) {
        cudaFuncSetAttribute(attn_f16, cudaFuncAttributeMaxDynamicSharedMemorySize, ATT_SMEM);
        cudaFuncSetAttribute(gemm_f16, cudaFuncAttributeMaxDynamicSharedMemorySize, FG_SMEM);
        smem_set = 1;
    }

    // 1) convert x and w_qkv to fp16
    {
        int n4 = ROWS * DMODEL / 4;
        convert_f16<<<(n4 + 255) / 256, 256>>>(x, xf, n4);
        int m4 = QKV_OUT * DMODEL / 4;
        convert_f16<<<(m4 + 255) / 256, 256>>>(w_qkv, wf, m4);
    }

    // 2) QKV projection: [4096,1536] x [2304,1536]^T
    {
        dim3 grid(QKV_OUT / 128, ROWS / 128);   // 18 x 32
        gemm_f16<<<grid, 256, FG_SMEM>>>(xf, wf, qkv, ROWS, QKV_OUT, DMODEL);
    }

    // 3) RoPE
    {
        int total = ROWS * 20 * 48;
        rope_kernel<<<(total + 255) / 256, 256>>>(qkv, gh, gw);
    }

    // 4) FP16 flash attention -> fp16 A-operand for O-proj
    {
        dim3 grid(SEQ / AQT, NHEADS, BATCH);    // 16 x 16 x 2
        attn_f16<<<grid, 256, ATT_SMEM>>>(qkv, (unsigned*)af);
    }

    // 5) convert w_o to fp16 (reuses weight buffer; stream-ordered after gemm1)
    {
        int m4 = DMODEL * DMODEL / 4;
        convert_f16<<<(m4 + 255) / 256, 256>>>(w_o, wf, m4);
    }

    // 6) Output projection: [4096,1536] x [1536,1536]^T
    {
        dim3 grid(DMODEL / 128, ROWS / 128);    // 12 x 32
        gemm_f16<<<grid, 256, FG_SMEM>>>(af, wf, out, ROWS, DMODEL, DMODEL);
    }
}